// round 3
// baseline (speedup 1.0000x reference)
#include <cuda_runtime.h>
#include <cstdint>

// ---------------------------------------------------------------------------
// FlexibleWaveConv2d, round 2.
//   K1a k_dwt  : x(32,128,128,128) -> A[s][pos][k=i][b]  (4x4 block Haar, tf32-rna)
//   K1b k_wprep: w_s(i,o,16,16)    -> Wt[s][uv][k=i][o]  (transpose, tf32-rna)
//   K2  k_fused: per (x, y-pair): for s in 0..3 build BOTH interpolated W
//                matrices from the 6 shared taps, run 2 GEMMs [32x128]x[128x128]
//                (tf32 mma.sync m16n8k8) into per-s register accumulators,
//                then do the full 2-level IDWT recombination in registers and
//                write out directly. No g_C, no separate idwt kernel.
// ---------------------------------------------------------------------------

#define S_A   (1024L*128*32)
#define N_A   (4L*1024*128*32)
#define N_WT  (4L*256*128*128)

static __device__ float g_A [N_A];   // [s][pos][k][b]
static __device__ float g_Wt[N_WT];  // [s][u*16+v][k][o]

__device__ __forceinline__ float rna_tf32(float x) {
    float r;
    asm("cvt.rna.tf32.f32 %0, %1;" : "=f"(r) : "f"(x));
    return r;
}

// jax bilinear 16->32: sample(j) = j/2 - 0.25, boundary renormalized.
__device__ __forceinline__ void taps(int j, int& i0, int& i1, float& c0, float& c1) {
    if (j == 0)        { i0 = 0;  i1 = 0;  c0 = 1.0f;  c1 = 0.0f; }
    else if (j == 31)  { i0 = 15; i1 = 15; c0 = 1.0f;  c1 = 0.0f; }
    else if (j & 1)    { int k = j >> 1; i0 = k;     i1 = k + 1; c0 = 0.75f; c1 = 0.25f; }
    else               { int k = j >> 1; i0 = k - 1; i1 = k;     c0 = 0.25f; c1 = 0.75f; }
}

// ---------------------------------------------------------------------------
// K1a: 4x4 block Haar. grid (32 x-rows, 128 channels), block 1024.
// ---------------------------------------------------------------------------
__global__ __launch_bounds__(1024) void k_dwt(const float* __restrict__ x) {
    const int xr = blockIdx.x;
    const int ci = blockIdx.y;
    __shared__ float vals[4][32][33];

    const int tid = threadIdx.x;
    {
        const int b = tid >> 5, y = tid & 31;
        const float4* px = reinterpret_cast<const float4*>(x)
                         + ((long)(b * 128 + ci) * 128 + 4 * xr) * 32 + y;
        float4 r0 = px[0], r1 = px[32], r2 = px[64], r3 = px[96];
        float q00 = r0.x + r0.y + r1.x + r1.y;
        float q01 = r0.z + r0.w + r1.z + r1.w;
        float q10 = r2.x + r2.y + r3.x + r3.y;
        float q11 = r2.z + r2.w + r3.z + r3.w;
        vals[0][y][b] = rna_tf32(0.25f * (q00 + q01 + q10 + q11));
        vals[1][y][b] = rna_tf32(0.25f * (q00 - q01 + q10 - q11));
        vals[2][y][b] = rna_tf32(0.25f * (q00 + q01 - q10 - q11));
        vals[3][y][b] = rna_tf32(0.25f * (q00 - q01 - q10 + q11));
    }
    __syncthreads();
    {
        const int y2 = tid >> 5, b2 = tid & 31;
        const long base = ((long)(xr * 32 + y2) * 128 + ci) * 32 + b2;
        g_A[0 * S_A + base] = vals[0][y2][b2];
        g_A[1 * S_A + base] = vals[1][y2][b2];
        g_A[2 * S_A + base] = vals[2][y2][b2];
        g_A[3 * S_A + base] = vals[3][y2][b2];
    }
}

// ---------------------------------------------------------------------------
// K1b: weight transpose (i,o,u,v) -> [s][uv][k][o], tf32-rna.
// ---------------------------------------------------------------------------
__global__ __launch_bounds__(256) void k_wprep(const float* __restrict__ w0,
                                               const float* __restrict__ w1,
                                               const float* __restrict__ w2,
                                               const float* __restrict__ w3) {
    const int uvb = blockIdx.x, k = blockIdx.y, s = blockIdx.z;
    const float* w = (s == 0) ? w0 : (s == 1) ? w1 : (s == 2) ? w2 : w3;
    __shared__ float t[128][33];
    const int tid = threadIdx.x;
    const int uvl = tid & 31;
    const int uv0 = uvb * 32;
    for (int o = tid >> 5; o < 128; o += 8)
        t[o][uvl] = w[((long)k * 128 + o) * 256 + uv0 + uvl];
    __syncthreads();
    const int o = tid & 127;
    for (int j = tid >> 7; j < 32; j += 2)
        g_Wt[(((long)s * 256 + uv0 + j) * 128 + k) * 128 + o] = rna_tf32(t[o][j]);
}

// ---------------------------------------------------------------------------
// K2: fused GEMM + IDWT. grid (32 x, 16 y-pairs), block 512 (16 warps).
// smem: sA0,sA1 [128][36] + sW0,sW1 [128][128] = 167936 B.
// ---------------------------------------------------------------------------
#define K2_SMEM ((2 * 128 * 36 + 2 * 128 * 128) * 4)

__device__ __forceinline__ void mma_tf32(float acc[4], const uint32_t a[4],
                                         const uint32_t b[2]) {
    asm volatile(
        "mma.sync.aligned.m16n8k8.row.col.f32.tf32.tf32.f32 "
        "{%0,%1,%2,%3}, {%4,%5,%6,%7}, {%8,%9}, {%0,%1,%2,%3};\n"
        : "+f"(acc[0]), "+f"(acc[1]), "+f"(acc[2]), "+f"(acc[3])
        : "r"(a[0]), "r"(a[1]), "r"(a[2]), "r"(a[3]), "r"(b[0]), "r"(b[1]));
}

__global__ __launch_bounds__(512) void k_fused(float* __restrict__ out) {
    extern __shared__ float sm[];
    float* sA0 = sm;                   // [k][b] stride 36
    float* sA1 = sm + 128 * 36;
    float* sW0 = sm + 2 * 128 * 36;    // [k][o] stride 128
    float* sW1 = sW0 + 128 * 128;

    const int xr = blockIdx.x;         // 0..31
    const int rr = blockIdx.y;         // 0..15 : y-pair {2rr, 2rr+1}
    const int tid = threadIdx.x;

    // interp coefficients for the pair
    int u0, u1; float cu[2];
    taps(xr, u0, u1, cu[0], cu[1]);
    const int ul[2] = {u0, u1};

    int vlist[3] = {rr - 1, rr, rr + 1};
    float cv0[3] = {0.25f, 0.75f, 0.0f};
    float cv1[3] = {0.0f,  0.75f, 0.25f};
    if (rr == 0)  { vlist[0] = 0;  cv0[0] = 0.0f; cv0[1] = 1.0f; }
    if (rr == 15) { vlist[2] = 15; cv1[2] = 0.0f; cv1[1] = 1.0f; }

    const int warp = tid >> 5, lane = tid & 31;
    const int g = lane >> 2, q = lane & 3;
    const int posi = warp >> 3;            // which position of the pair
    const int ob = (warp & 7) << 4;        // 16 output cols per warp

    float acc[4][2][2][4];
#pragma unroll
    for (int s = 0; s < 4; s++)
#pragma unroll
        for (int m = 0; m < 2; m++)
#pragma unroll
            for (int n = 0; n < 2; n++)
#pragma unroll
                for (int i = 0; i < 4; i++) acc[s][m][n][i] = 0.0f;

    const float* sA_p = posi ? sA1 : sA0;
    const float* sW_p = posi ? sW1 : sW0;

#pragma unroll
    for (int s = 0; s < 4; s++) {
        // ---- stage A for both positions ----
        const float4* Ag0 = reinterpret_cast<const float4*>(
            g_A + ((long)s * 1024 + xr * 32 + 2 * rr) * 4096);
        const float4* Ag1 = Ag0 + 1024;
        for (int idx = tid; idx < 1024; idx += 512) {
            const int k = idx >> 3, b4 = (idx & 7) << 2;
            *reinterpret_cast<float4*>(&sA0[k * 36 + b4]) = Ag0[idx];
            *reinterpret_cast<float4*>(&sA1[k * 36 + b4]) = Ag1[idx];
        }

        // ---- build both interpolated W matrices from <=6 shared taps ----
        const float4* tp[6]; float ca[6], cb[6]; int nt = 0;
#pragma unroll
        for (int iu = 0; iu < 2; iu++) {
            if (cu[iu] == 0.0f) continue;
#pragma unroll
            for (int iv = 0; iv < 3; iv++) {
                const float a = cu[iu] * cv0[iv];
                const float b = cu[iu] * cv1[iv];
                if (a == 0.0f && b == 0.0f) continue;
                tp[nt] = reinterpret_cast<const float4*>(
                    g_Wt + ((long)s * 256 + ul[iu] * 16 + vlist[iv]) * 16384);
                ca[nt] = a; cb[nt] = b; nt++;
            }
        }
        for (int idx = tid; idx < 4096; idx += 512) {
            float4 a0 = make_float4(0.f, 0.f, 0.f, 0.f);
            float4 a1 = make_float4(0.f, 0.f, 0.f, 0.f);
            for (int t = 0; t < nt; t++) {
                const float4 v = tp[t][idx];
                const float c0 = ca[t], c1 = cb[t];
                a0.x += c0 * v.x; a0.y += c0 * v.y; a0.z += c0 * v.z; a0.w += c0 * v.w;
                a1.x += c1 * v.x; a1.y += c1 * v.y; a1.z += c1 * v.z; a1.w += c1 * v.w;
            }
            float4 r0, r1;
            r0.x = rna_tf32(a0.x); r0.y = rna_tf32(a0.y);
            r0.z = rna_tf32(a0.z); r0.w = rna_tf32(a0.w);
            r1.x = rna_tf32(a1.x); r1.y = rna_tf32(a1.y);
            r1.z = rna_tf32(a1.z); r1.w = rna_tf32(a1.w);
            reinterpret_cast<float4*>(sW0)[idx] = r0;
            reinterpret_cast<float4*>(sW1)[idx] = r1;
        }
        __syncthreads();

        // ---- MMA: each warp does 16 o-cols of its position's GEMM ----
#pragma unroll 4
        for (int k0 = 0; k0 < 128; k0 += 8) {
            uint32_t af[2][4];
#pragma unroll
            for (int m = 0; m < 2; m++) {
                const int r0 = m * 16 + g;
                af[m][0] = __float_as_uint(sA_p[(k0 + q) * 36 + r0]);
                af[m][1] = __float_as_uint(sA_p[(k0 + q) * 36 + r0 + 8]);
                af[m][2] = __float_as_uint(sA_p[(k0 + q + 4) * 36 + r0]);
                af[m][3] = __float_as_uint(sA_p[(k0 + q + 4) * 36 + r0 + 8]);
            }
            uint32_t bf[2][2];
#pragma unroll
            for (int n = 0; n < 2; n++) {
                const int oc = ob + n * 8 + g;
                bf[n][0] = __float_as_uint(sW_p[(k0 + q) * 128 + oc]);
                bf[n][1] = __float_as_uint(sW_p[(k0 + q + 4) * 128 + oc]);
            }
#pragma unroll
            for (int m = 0; m < 2; m++)
#pragma unroll
                for (int n = 0; n < 2; n++) mma_tf32(acc[s][m][n], af[m], bf[n]);
        }
        __syncthreads();   // before smem reuse next s
    }

    // ---- fused 2-level IDWT epilogue, direct store ----
    // out[b][o][4x+2a+d][4y+2c+e] = 0.25*(ll +(-1)^c lh +(-1)^a hl +(-1)^(a+c) hh)
    const int y = 2 * rr + posi;
#pragma unroll
    for (int m = 0; m < 2; m++)
#pragma unroll
        for (int n = 0; n < 2; n++)
#pragma unroll
            for (int i = 0; i < 4; i++) {
                const int row = m * 16 + g + ((i >> 1) << 3);   // batch b
                const int col = ob + n * 8 + q * 2 + (i & 1);   // out channel o
                const float ll = acc[0][m][n][i], lh = acc[1][m][n][i];
                const float hl = acc[2][m][n][i], hh = acc[3][m][n][i];
                const float e00 = 0.25f * (ll + lh + hl + hh);
                const float e01 = 0.25f * (ll - lh + hl - hh);
                const float e10 = 0.25f * (ll + lh - hl - hh);
                const float e11 = 0.25f * (ll - lh - hl + hh);
                float* p = out + (((long)(row * 128 + col) * 128 + 4 * xr) * 128 + 4 * y);
                const float4 top = make_float4(e00, e00, e01, e01);
                const float4 bot = make_float4(e10, e10, e11, e11);
                *reinterpret_cast<float4*>(p)       = top;
                *reinterpret_cast<float4*>(p + 128) = top;
                *reinterpret_cast<float4*>(p + 256) = bot;
                *reinterpret_cast<float4*>(p + 384) = bot;
            }
}

// ---------------------------------------------------------------------------
extern "C" void kernel_launch(void* const* d_in, const int* in_sizes, int n_in,
                              void* d_out, int out_size) {
    (void)in_sizes; (void)n_in; (void)out_size;
    const float* x  = (const float*)d_in[0];
    const float* w1 = (const float*)d_in[1];
    const float* w2 = (const float*)d_in[2];
    const float* w3 = (const float*)d_in[3];
    const float* w4 = (const float*)d_in[4];

    cudaFuncSetAttribute(k_fused, cudaFuncAttributeMaxDynamicSharedMemorySize, K2_SMEM);

    k_dwt  <<<dim3(32, 128), 1024>>>(x);
    k_wprep<<<dim3(8, 128, 4), 256>>>(w1, w2, w3, w4);
    k_fused<<<dim3(32, 16), 512, K2_SMEM>>>((float*)d_out);
}

// round 5
// speedup vs baseline: 1.6402x; 1.6402x over previous
#include <cuda_runtime.h>
#include <cstdint>

// ---------------------------------------------------------------------------
// FlexibleWaveConv2d, round 3.
//   K1a k_dwt   : x -> A[s][pos][k][b]           (4x4 block Haar, tf32-rna)
//   K1b k_wprep : w_s -> Wt[s][uv][k][o]         (transpose, tf32-rna)
//   K2  k_gemm  : per (s, x, y-pair): GEMM with K extended over raw taps,
//                 coefficients folded into B-fragments. cp.async streaming,
//                 A fragment-packed + register-resident across taps,
//                 each warp computes BOTH positions of the pair.
//   K3  k_idwt  : C -> out, block=(xr,b), smem-staged, coalesced.
// ---------------------------------------------------------------------------

#define S_A   (1024L*128*32)
#define N_A   (4L*1024*128*32)
#define N_WT  (4L*256*128*128)
#define N_C   (4L*1024*32*128)

static __device__ float g_A [N_A];   // [s][pos][k][b]
static __device__ float g_Wt[N_WT];  // [s][u*16+v][k][o]
static __device__ float g_C [N_C];   // [s][pos][b][o]

__device__ __forceinline__ float rna_tf32(float x) {
    float r;
    asm("cvt.rna.tf32.f32 %0, %1;" : "=f"(r) : "f"(x));
    return r;
}

__device__ __forceinline__ void taps(int j, int& i0, int& i1, float& c0, float& c1) {
    if (j == 0)        { i0 = 0;  i1 = 0;  c0 = 1.0f;  c1 = 0.0f; }
    else if (j == 31)  { i0 = 15; i1 = 15; c0 = 1.0f;  c1 = 0.0f; }
    else if (j & 1)    { int k = j >> 1; i0 = k;     i1 = k + 1; c0 = 0.75f; c1 = 0.25f; }
    else               { int k = j >> 1; i0 = k - 1; i1 = k;     c0 = 0.25f; c1 = 0.75f; }
}

// ---------------------------------------------------------------------------
// K1a: 4x4 block Haar. grid (32 x-rows, 128 channels), block 1024.
// ---------------------------------------------------------------------------
__global__ __launch_bounds__(1024) void k_dwt(const float* __restrict__ x) {
    const int xr = blockIdx.x;
    const int ci = blockIdx.y;
    __shared__ float vals[4][32][33];

    const int tid = threadIdx.x;
    {
        const int b = tid >> 5, y = tid & 31;
        const float4* px = reinterpret_cast<const float4*>(x)
                         + ((long)(b * 128 + ci) * 128 + 4 * xr) * 32 + y;
        float4 r0 = px[0], r1 = px[32], r2 = px[64], r3 = px[96];
        float q00 = r0.x + r0.y + r1.x + r1.y;
        float q01 = r0.z + r0.w + r1.z + r1.w;
        float q10 = r2.x + r2.y + r3.x + r3.y;
        float q11 = r2.z + r2.w + r3.z + r3.w;
        vals[0][y][b] = rna_tf32(0.25f * (q00 + q01 + q10 + q11));
        vals[1][y][b] = rna_tf32(0.25f * (q00 - q01 + q10 - q11));
        vals[2][y][b] = rna_tf32(0.25f * (q00 + q01 - q10 - q11));
        vals[3][y][b] = rna_tf32(0.25f * (q00 - q01 - q10 + q11));
    }
    __syncthreads();
    {
        const int y2 = tid >> 5, b2 = tid & 31;
        const long base = ((long)(xr * 32 + y2) * 128 + ci) * 32 + b2;
        g_A[0 * S_A + base] = vals[0][y2][b2];
        g_A[1 * S_A + base] = vals[1][y2][b2];
        g_A[2 * S_A + base] = vals[2][y2][b2];
        g_A[3 * S_A + base] = vals[3][y2][b2];
    }
}

// ---------------------------------------------------------------------------
// K1b: weight transpose (i,o,u,v) -> [s][uv][k][o], tf32-rna.
// ---------------------------------------------------------------------------
__global__ __launch_bounds__(256) void k_wprep(const float* __restrict__ w0,
                                               const float* __restrict__ w1,
                                               const float* __restrict__ w2,
                                               const float* __restrict__ w3) {
    const int uvb = blockIdx.x, k = blockIdx.y, s = blockIdx.z;
    const float* w = (s == 0) ? w0 : (s == 1) ? w1 : (s == 2) ? w2 : w3;
    __shared__ float t[128][33];
    const int tid = threadIdx.x;
    const int uvl = tid & 31;
    const int uv0 = uvb * 32;
    for (int o = tid >> 5; o < 128; o += 8)
        t[o][uvl] = w[((long)k * 128 + o) * 256 + uv0 + uvl];
    __syncthreads();
    const int o = tid & 127;
    for (int j = tid >> 7; j < 32; j += 2)
        g_Wt[(((long)s * 256 + uv0 + j) * 128 + k) * 128 + o] = rna_tf32(t[o][j]);
}

// ---------------------------------------------------------------------------
// K2: streaming-tap GEMM.
// grid (16 rr, 32 xr, 4 s), block 256 (8 warps). Each warp: both positions
// of the y-pair, 16 o-cols, M=32, K = 4 taps x 128.
// smem (floats): sAp 8192 | sScr 9216 (raw A stage, then 2x4224 B buffers)
//                | tc0 6 | tc1 6 | tb 6 longs
// ---------------------------------------------------------------------------
#define KG_SMEM_FLOATS (8192 + 9216 + 6 + 6 + 12)
#define KG_SMEM (KG_SMEM_FLOATS * 4)

__device__ __forceinline__ void mma_tf32(float acc[4], const uint32_t a[4],
                                         const uint32_t b[2]) {
    asm volatile(
        "mma.sync.aligned.m16n8k8.row.col.f32.tf32.tf32.f32 "
        "{%0,%1,%2,%3}, {%4,%5,%6,%7}, {%8,%9}, {%0,%1,%2,%3};\n"
        : "+f"(acc[0]), "+f"(acc[1]), "+f"(acc[2]), "+f"(acc[3])
        : "r"(a[0]), "r"(a[1]), "r"(a[2]), "r"(a[3]), "r"(b[0]), "r"(b[1]));
}

__device__ __forceinline__ uint32_t scale_tf32(float c, float v) {
    if (c == 1.0f) return __float_as_uint(v);
    return __float_as_uint(rna_tf32(c * v));
}

__device__ __forceinline__ void cpasync16(uint32_t dst, const void* src) {
    asm volatile("cp.async.cg.shared.global [%0], [%1], 16;"
                 :: "r"(dst), "l"(src));
}

__global__ __launch_bounds__(256, 2) void k_gemm() {
    extern __shared__ float sm[];
    float* sAp  = sm;           // packed A fragments, 2 pos x 4096
    float* sScr = sm + 8192;    // raw A stage (9216) / B double buffer (2x4224)
    float* sTc0 = sm + 17408;
    float* sTc1 = sm + 17414;
    long*  sTb  = (long*)(sm + 17420);

    const int rr = blockIdx.x;     // y-pair
    const int xr = blockIdx.y;
    const int s  = blockIdx.z;
    const int tid = threadIdx.x;

    // ---- tap list (thread 0 -> smem) ----
    int nt;
    {
        int u0, u1; float cuu[2];
        taps(xr, u0, u1, cuu[0], cuu[1]);
        const int ul[2] = {u0, u1};
        int vl[3] = {rr - 1, rr, rr + 1};
        float cv0[3] = {0.25f, 0.75f, 0.0f};
        float cv1[3] = {0.0f,  0.75f, 0.25f};
        if (rr == 0)  { vl[0] = 0;  cv0[0] = 0.0f; cv0[1] = 1.0f; }
        if (rr == 15) { vl[2] = 15; cv1[2] = 0.0f; cv1[1] = 1.0f; }
        int n = 0;
        for (int iu = 0; iu < 2; iu++) {
            if (cuu[iu] == 0.0f) continue;
            for (int iv = 0; iv < 3; iv++) {
                const float a = cuu[iu] * cv0[iv];
                const float b = cuu[iu] * cv1[iv];
                if (a == 0.0f && b == 0.0f) continue;
                if (tid == 0) {
                    sTc0[n] = a; sTc1[n] = b;
                    sTb[n] = (long)(g_Wt + ((long)s * 256 + ul[iu] * 16 + vl[iv]) * 16384);
                }
                n++;
            }
        }
        nt = n;
    }

    // ---- stage raw A (both positions) into sScr, stride 36 ----
    {
        const float4* Ag = reinterpret_cast<const float4*>(
            g_A + ((long)s * 1024 + xr * 32 + 2 * rr) * 4096);
        for (int idx = tid; idx < 2048; idx += 256) {
            const int pos = idx >> 10, r = idx & 1023;
            const int k = r >> 3, b4 = (r & 7) << 2;
            *reinterpret_cast<float4*>(&sScr[pos * 4608 + k * 36 + b4]) = Ag[idx];
        }
    }
    __syncthreads();

    // ---- repack A into fragment order: sAp[pos*4096 + ((ksg*2+m)*32+lane)*4 + comp]
    //      comp: a0=(m16+g, 8ksg+q) a1=(+8 row) a2=(col+4) a3=(both) ----
    for (int i = 0; i < 8; i++) {
        const int fid = i * 256 + tid;
        const int pos = fid >> 10, r = fid & 1023;
        const int ksg = r >> 6, m = (r >> 5) & 1, lane = r & 31;
        const int g = lane >> 2, q = lane & 3;
        const float* rb = sScr + pos * 4608;
        float4 v;
        v.x = rb[(ksg * 8 + q) * 36 + m * 16 + g];
        v.y = rb[(ksg * 8 + q) * 36 + m * 16 + 8 + g];
        v.z = rb[(ksg * 8 + q + 4) * 36 + m * 16 + g];
        v.w = rb[(ksg * 8 + q + 4) * 36 + m * 16 + 8 + g];
        *reinterpret_cast<float4*>(&sAp[fid * 4]) = v;
    }
    __syncthreads();   // raw A dead; sScr becomes B double buffer

    const int warp = tid >> 5, lane = tid & 31;
    const int g = lane >> 2, q = lane & 3;
    const int ob = warp << 4;     // 16 o-cols per warp

    float acc[2][2][2][4];        // [pos][m][n][4]
#pragma unroll
    for (int p = 0; p < 2; p++)
#pragma unroll
        for (int m = 0; m < 2; m++)
#pragma unroll
            for (int n = 0; n < 2; n++)
#pragma unroll
                for (int i = 0; i < 4; i++) acc[p][m][n][i] = 0.0f;

    const int C = nt * 4;         // chunks: kc-major, tap-inner

    auto issue = [&](int ci) {
        const int kc = ci / nt;
        const int t  = ci - kc * nt;
        const float* src = reinterpret_cast<const float*>(sTb[t]) + kc * 4096;
        float* dst = sScr + (ci & 1) * 4224;
#pragma unroll
        for (int j = 0; j < 4; j++) {
            const int seg = tid + j * 256;
            const int kr = seg >> 5, sg = seg & 31;
            cpasync16((uint32_t)__cvta_generic_to_shared(dst + kr * 132 + sg * 4),
                      src + kr * 128 + sg * 4);
        }
        asm volatile("cp.async.commit_group;");
    };

    uint32_t aF[2][4][2][4];      // [pos][ks][m][4] A fragments for current kc

    issue(0);
    int kc = 0, t = 0;
    for (int ci = 0; ci < C; ci++) {
        if (ci + 1 < C) {
            issue(ci + 1);
            asm volatile("cp.async.wait_group 1;");
        } else {
            asm volatile("cp.async.wait_group 0;");
        }
        __syncthreads();

        if (t == 0) {   // new kc: load A fragments once
#pragma unroll
            for (int p = 0; p < 2; p++)
#pragma unroll
                for (int ks = 0; ks < 4; ks++)
#pragma unroll
                    for (int m = 0; m < 2; m++) {
                        const float4 v = *reinterpret_cast<const float4*>(
                            &sAp[(p * 1024 + ((kc * 4 + ks) * 2 + m) * 32 + lane) * 4]);
                        aF[p][ks][m][0] = __float_as_uint(v.x);
                        aF[p][ks][m][1] = __float_as_uint(v.y);
                        aF[p][ks][m][2] = __float_as_uint(v.z);
                        aF[p][ks][m][3] = __float_as_uint(v.w);
                    }
        }

        const float c0t = sTc0[t], c1t = sTc1[t];
        const float* Bb = sScr + (ci & 1) * 4224;

#pragma unroll
        for (int ks = 0; ks < 4; ks++) {
            const int k0 = ks * 8;
            float br[2][2];
#pragma unroll
            for (int n = 0; n < 2; n++) {
                const int oc = ob + n * 8 + g;
                br[n][0] = Bb[(k0 + q) * 132 + oc];
                br[n][1] = Bb[(k0 + q + 4) * 132 + oc];
            }
            if (c0t != 0.0f) {
                uint32_t bf[2][2];
#pragma unroll
                for (int n = 0; n < 2; n++) {
                    bf[n][0] = scale_tf32(c0t, br[n][0]);
                    bf[n][1] = scale_tf32(c0t, br[n][1]);
                }
#pragma unroll
                for (int m = 0; m < 2; m++)
#pragma unroll
                    for (int n = 0; n < 2; n++) mma_tf32(acc[0][m][n], aF[0][ks][m], bf[n]);
            }
            if (c1t != 0.0f) {
                uint32_t bf[2][2];
#pragma unroll
                for (int n = 0; n < 2; n++) {
                    bf[n][0] = scale_tf32(c1t, br[n][0]);
                    bf[n][1] = scale_tf32(c1t, br[n][1]);
                }
#pragma unroll
                for (int m = 0; m < 2; m++)
#pragma unroll
                    for (int n = 0; n < 2; n++) mma_tf32(acc[1][m][n], aF[1][ks][m], bf[n]);
            }
        }
        __syncthreads();   // MMA done before this buffer is overwritten

        if (++t == nt) { t = 0; kc++; }
    }

    // ---- store C[s][pos][b][o] ----
#pragma unroll
    for (int p = 0; p < 2; p++) {
        float* Cb = g_C + ((long)s * 1024 + xr * 32 + 2 * rr + p) * 4096;
#pragma unroll
        for (int m = 0; m < 2; m++)
#pragma unroll
            for (int n = 0; n < 2; n++) {
                const int row = m * 16 + g;
                const int col = ob + n * 8 + q * 2;
                *reinterpret_cast<float2*>(&Cb[row * 128 + col]) =
                    make_float2(acc[p][m][n][0], acc[p][m][n][1]);
                *reinterpret_cast<float2*>(&Cb[(row + 8) * 128 + col]) =
                    make_float2(acc[p][m][n][2], acc[p][m][n][3]);
            }
    }
}

// ---------------------------------------------------------------------------
// K3: idwt + zero-idwt. grid (32 xr, 32 b), block 256.
// smem: sC[4*32][130] = 66560 B (dynamic). 2-way LDS conflicts only.
// ---------------------------------------------------------------------------
#define K3_SMEM (4 * 32 * 130 * 4)

__global__ __launch_bounds__(256) void k_idwt(float* __restrict__ out) {
    extern __shared__ float sC[];   // [(s*32+y)][o] stride 130
    const int xr = blockIdx.x, b = blockIdx.y;
    const int tid = threadIdx.x;

    const float4* Cg = reinterpret_cast<const float4*>(g_C);
    for (int i = 0; i < 16; i++) {
        const int fid = i * 256 + tid;
        const int row = fid >> 5, c4 = fid & 31;     // row = s*32+y
        const int ss = row >> 5, y = row & 31;
        const float4 v = Cg[(((long)ss * 1024 + xr * 32 + y) * 32 + b) * 32 + c4];
        float* d = &sC[row * 130 + c4 * 4];
        *reinterpret_cast<float2*>(d)     = make_float2(v.x, v.y);
        *reinterpret_cast<float2*>(d + 2) = make_float2(v.z, v.w);
    }
    __syncthreads();

    const int y = tid & 31;
    const int oh = tid >> 5;        // 0..7
    const long ob0 = ((long)b * 128) * 16384 + (4 * xr) * 128 + 4 * y;

#pragma unroll 4
    for (int j = 0; j < 16; j++) {
        const int o = oh * 16 + j;
        const float ll = sC[(0 * 32 + y) * 130 + o];
        const float lh = sC[(1 * 32 + y) * 130 + o];
        const float hl = sC[(2 * 32 + y) * 130 + o];
        const float hh = sC[(3 * 32 + y) * 130 + o];
        const float e00 = 0.25f * (ll + lh + hl + hh);
        const float e01 = 0.25f * (ll - lh + hl - hh);
        const float e10 = 0.25f * (ll + lh - hl - hh);
        const float e11 = 0.25f * (ll - lh - hl + hh);
        float* p = out + ob0 + (long)o * 16384;
        const float4 top = make_float4(e00, e00, e01, e01);
        const float4 bot = make_float4(e10, e10, e11, e11);
        *reinterpret_cast<float4*>(p)       = top;
        *reinterpret_cast<float4*>(p + 128) = top;
        *reinterpret_cast<float4*>(p + 256) = bot;
        *reinterpret_cast<float4*>(p + 384) = bot;
    }
}

// ---------------------------------------------------------------------------
extern "C" void kernel_launch(void* const* d_in, const int* in_sizes, int n_in,
                              void* d_out, int out_size) {
    (void)in_sizes; (void)n_in; (void)out_size;
    const float* x  = (const float*)d_in[0];
    const float* w1 = (const float*)d_in[1];
    const float* w2 = (const float*)d_in[2];
    const float* w3 = (const float*)d_in[3];
    const float* w4 = (const float*)d_in[4];

    cudaFuncSetAttribute(k_gemm, cudaFuncAttributeMaxDynamicSharedMemorySize, KG_SMEM);
    cudaFuncSetAttribute(k_idwt, cudaFuncAttributeMaxDynamicSharedMemorySize, K3_SMEM);

    k_dwt  <<<dim3(32, 128), 1024>>>(x);
    k_wprep<<<dim3(8, 128, 4), 256>>>(w1, w2, w3, w4);
    k_gemm <<<dim3(16, 32, 4), 256, KG_SMEM>>>();
    k_idwt <<<dim3(32, 32), 256, K3_SMEM>>>((float*)d_out);
}

// round 6
// speedup vs baseline: 2.0497x; 1.2497x over previous
#include <cuda_runtime.h>
#include <cstdint>

// ---------------------------------------------------------------------------
// FlexibleWaveConv2d, round 6.
//   K1a k_dwt   : x -> A[s][pos][k][b]           (4x4 block Haar, tf32-rna)
//   K1b k_wprep : w_s -> Wt[s][uv][k][o]         (transpose, tf32-rna)
//   K2  k_gemm  : per (s, xr, y-pair): stream raw tap k-chunks (cp.async,
//                 read-own-bytes, no bar), accumulate BOTH positions'
//                 interpolated W chunks in registers, STS once per k-chunk,
//                 then minimal MMA (1x work, tf32 m16n8k8) -> g_C.
//   K3  k_idwt  : C -> out, o-halved blocks for occupancy, coalesced.
// ---------------------------------------------------------------------------

#define S_A   (1024L*128*32)
#define N_A   (4L*1024*128*32)
#define N_WT  (4L*256*128*128)
#define N_C   (4L*1024*32*128)

static __device__ float g_A [N_A];   // [s][pos][k][b]
static __device__ float g_Wt[N_WT];  // [s][u*16+v][k][o]
static __device__ float g_C [N_C];   // [s][pos][b][o]

__device__ __forceinline__ float rna_tf32(float x) {
    float r;
    asm("cvt.rna.tf32.f32 %0, %1;" : "=f"(r) : "f"(x));
    return r;
}

__device__ __forceinline__ void taps(int j, int& i0, int& i1, float& c0, float& c1) {
    if (j == 0)        { i0 = 0;  i1 = 0;  c0 = 1.0f;  c1 = 0.0f; }
    else if (j == 31)  { i0 = 15; i1 = 15; c0 = 1.0f;  c1 = 0.0f; }
    else if (j & 1)    { int k = j >> 1; i0 = k;     i1 = k + 1; c0 = 0.75f; c1 = 0.25f; }
    else               { int k = j >> 1; i0 = k - 1; i1 = k;     c0 = 0.25f; c1 = 0.75f; }
}

// ---------------------------------------------------------------------------
// K1a: 4x4 block Haar. grid (32 x-rows, 128 channels), block 1024.
// ---------------------------------------------------------------------------
__global__ __launch_bounds__(1024) void k_dwt(const float* __restrict__ x) {
    const int xr = blockIdx.x;
    const int ci = blockIdx.y;
    __shared__ float vals[4][32][33];

    const int tid = threadIdx.x;
    {
        const int b = tid >> 5, y = tid & 31;
        const float4* px = reinterpret_cast<const float4*>(x)
                         + ((long)(b * 128 + ci) * 128 + 4 * xr) * 32 + y;
        float4 r0 = px[0], r1 = px[32], r2 = px[64], r3 = px[96];
        float q00 = r0.x + r0.y + r1.x + r1.y;
        float q01 = r0.z + r0.w + r1.z + r1.w;
        float q10 = r2.x + r2.y + r3.x + r3.y;
        float q11 = r2.z + r2.w + r3.z + r3.w;
        vals[0][y][b] = rna_tf32(0.25f * (q00 + q01 + q10 + q11));
        vals[1][y][b] = rna_tf32(0.25f * (q00 - q01 + q10 - q11));
        vals[2][y][b] = rna_tf32(0.25f * (q00 + q01 - q10 - q11));
        vals[3][y][b] = rna_tf32(0.25f * (q00 - q01 - q10 + q11));
    }
    __syncthreads();
    {
        const int y2 = tid >> 5, b2 = tid & 31;
        const long base = ((long)(xr * 32 + y2) * 128 + ci) * 32 + b2;
        g_A[0 * S_A + base] = vals[0][y2][b2];
        g_A[1 * S_A + base] = vals[1][y2][b2];
        g_A[2 * S_A + base] = vals[2][y2][b2];
        g_A[3 * S_A + base] = vals[3][y2][b2];
    }
}

// ---------------------------------------------------------------------------
// K1b: weight transpose (i,o,u,v) -> [s][uv][k][o], tf32-rna.
// ---------------------------------------------------------------------------
__global__ __launch_bounds__(256) void k_wprep(const float* __restrict__ w0,
                                               const float* __restrict__ w1,
                                               const float* __restrict__ w2,
                                               const float* __restrict__ w3) {
    const int uvb = blockIdx.x, k = blockIdx.y, s = blockIdx.z;
    const float* w = (s == 0) ? w0 : (s == 1) ? w1 : (s == 2) ? w2 : w3;
    __shared__ float t[128][33];
    const int tid = threadIdx.x;
    const int uvl = tid & 31;
    const int uv0 = uvb * 32;
    for (int o = tid >> 5; o < 128; o += 8)
        t[o][uvl] = w[((long)k * 128 + o) * 256 + uv0 + uvl];
    __syncthreads();
    const int o = tid & 127;
    for (int j = tid >> 7; j < 32; j += 2)
        g_Wt[(((long)s * 256 + uv0 + j) * 128 + k) * 128 + o] = rna_tf32(t[o][j]);
}

// ---------------------------------------------------------------------------
// K2: interp-in-registers streaming GEMM.
// grid (16 rr, 32 xr, 4 s), block 256 (8 warps), 2 CTAs/SM.
// smem floats: sAp 8192 | sTap 2x4224 | sW 2x4224 | meta
// ---------------------------------------------------------------------------
#define KG_SMEM_FLOATS (8192 + 8448 + 8448 + 6 + 6 + 12)
#define KG_SMEM (KG_SMEM_FLOATS * 4)

__device__ __forceinline__ void mma_tf32(float acc[4], const uint32_t a[4],
                                         const uint32_t b[2]) {
    asm volatile(
        "mma.sync.aligned.m16n8k8.row.col.f32.tf32.tf32.f32 "
        "{%0,%1,%2,%3}, {%4,%5,%6,%7}, {%8,%9}, {%0,%1,%2,%3};\n"
        : "+f"(acc[0]), "+f"(acc[1]), "+f"(acc[2]), "+f"(acc[3])
        : "r"(a[0]), "r"(a[1]), "r"(a[2]), "r"(a[3]), "r"(b[0]), "r"(b[1]));
}

__device__ __forceinline__ void cpasync16(uint32_t dst, const void* src) {
    asm volatile("cp.async.cg.shared.global [%0], [%1], 16;"
                 :: "r"(dst), "l"(src));
}

__global__ __launch_bounds__(256, 2) void k_gemm() {
    extern __shared__ float sm[];
    float* sAp  = sm;                    // packed A fragments, 2 pos x 4096
    float* sTap = sm + 8192;             // tap double buffer 2 x 4224
    float* sW   = sm + 16640;            // interp W chunk, 2 pos x 4224
    float* sTc0 = sm + 25088;
    float* sTc1 = sm + 25094;
    const float** sTb = (const float**)(sm + 25100);

    const int rr = blockIdx.x;
    const int xr = blockIdx.y;
    const int s  = blockIdx.z;
    const int tid = threadIdx.x;

    // ---- tap list -> smem (thread 0) ----
    int nt;
    {
        int u0, u1; float cuu[2];
        taps(xr, u0, u1, cuu[0], cuu[1]);
        const int ul[2] = {u0, u1};
        int vl[3] = {rr - 1, rr, rr + 1};
        float cv0[3] = {0.25f, 0.75f, 0.0f};
        float cv1[3] = {0.0f,  0.75f, 0.25f};
        if (rr == 0)  { vl[0] = 0;  cv0[0] = 0.0f; cv0[1] = 1.0f; }
        if (rr == 15) { vl[2] = 15; cv1[2] = 0.0f; cv1[1] = 1.0f; }
        int n = 0;
        for (int iu = 0; iu < 2; iu++) {
            if (cuu[iu] == 0.0f) continue;
            for (int iv = 0; iv < 3; iv++) {
                const float a = cuu[iu] * cv0[iv];
                const float b = cuu[iu] * cv1[iv];
                if (a == 0.0f && b == 0.0f) continue;
                if (tid == 0) {
                    sTc0[n] = a; sTc1[n] = b;
                    sTb[n] = g_Wt + ((long)s * 256 + ul[iu] * 16 + vl[iv]) * 16384;
                }
                n++;
            }
        }
        nt = n;
    }

    // ---- stage raw A into sTap region (dead until mainloop) ----
    {
        const float4* Ag = reinterpret_cast<const float4*>(
            g_A + ((long)s * 1024 + xr * 32 + 2 * rr) * 4096);
        float* raw = sTap;                       // 9216 floats scratch
        for (int idx = tid; idx < 2048; idx += 256) {
            const int pos = idx >> 10, r = idx & 1023;
            const int k = r >> 3, b4 = (r & 7) << 2;
            *reinterpret_cast<float4*>(&raw[pos * 4608 + k * 36 + b4]) =
                Ag[idx];
        }
    }
    __syncthreads();     // meta + raw A visible

    const int C = nt * 4;

    auto issue = [&](int ci) {
        const int kc = ci >> 2 >= 0 ? ci / nt : 0;   // kc = ci / nt
        const int t  = ci - kc * nt;
        const float* src = sTb[t] + kc * 4096;
        float* dst = sTap + (ci & 1) * 4224;
#pragma unroll
        for (int j = 0; j < 4; j++) {
            const int idx = tid + j * 256;
            const int kr = idx >> 5, sg = idx & 31;
            cpasync16((uint32_t)__cvta_generic_to_shared(dst + kr * 132 + sg * 4),
                      src + idx * 4);
        }
        asm volatile("cp.async.commit_group;");
    };

    // ---- repack A into fragment order (overlaps nothing yet; issue after) ----
    // NOTE: cannot issue tap chunks before repack finishes (same smem).
    {
        const float* raw = sTap;
        float4 tmp[8];
#pragma unroll
        for (int i = 0; i < 8; i++) {
            const int fid = i * 256 + tid;
            const int pos = fid >> 10, r = fid & 1023;
            const int ksg = r >> 6, m = (r >> 5) & 1, lane = r & 31;
            const int g = lane >> 2, q = lane & 3;
            const float* rb = raw + pos * 4608;
            tmp[i].x = rb[(ksg * 8 + q) * 36 + m * 16 + g];
            tmp[i].y = rb[(ksg * 8 + q) * 36 + m * 16 + 8 + g];
            tmp[i].z = rb[(ksg * 8 + q + 4) * 36 + m * 16 + g];
            tmp[i].w = rb[(ksg * 8 + q + 4) * 36 + m * 16 + 8 + g];
        }
#pragma unroll
        for (int i = 0; i < 8; i++)
            *reinterpret_cast<float4*>(&sAp[(i * 256 + tid) * 4]) = tmp[i];
    }
    __syncthreads();     // raw A dead; sTap becomes tap double buffer

    const int warp = tid >> 5, lane = tid & 31;
    const int g = lane >> 2, q = lane & 3;
    const int ob = warp << 4;

    float acc[2][2][2][4];
#pragma unroll
    for (int p = 0; p < 2; p++)
#pragma unroll
        for (int m = 0; m < 2; m++)
#pragma unroll
            for (int n = 0; n < 2; n++)
#pragma unroll
                for (int i = 0; i < 4; i++) acc[p][m][n][i] = 0.0f;

    float4 w0a[4], w1a[4];
    issue(0);
    issue(1);

    int kc = 0, t = 0;
    for (int ci = 0; ci < C; ci++) {
        if (ci + 2 <= C) asm volatile("cp.async.wait_group 1;");
        else             asm volatile("cp.async.wait_group 0;");

        const float c0t = sTc0[t], c1t = sTc1[t];
        const float* buf = sTap + (ci & 1) * 4224;
#pragma unroll
        for (int j = 0; j < 4; j++) {
            const int idx = tid + j * 256;
            const int kr = idx >> 5, sg = idx & 31;
            const float4 v = *reinterpret_cast<const float4*>(&buf[kr * 132 + sg * 4]);
            if (t == 0) {
                w0a[j] = make_float4(c0t * v.x, c0t * v.y, c0t * v.z, c0t * v.w);
                w1a[j] = make_float4(c1t * v.x, c1t * v.y, c1t * v.z, c1t * v.w);
            } else {
                w0a[j].x += c0t * v.x; w0a[j].y += c0t * v.y;
                w0a[j].z += c0t * v.z; w0a[j].w += c0t * v.w;
                w1a[j].x += c1t * v.x; w1a[j].y += c1t * v.y;
                w1a[j].z += c1t * v.z; w1a[j].w += c1t * v.w;
            }
        }
        if (ci + 2 < C) issue(ci + 2);   // safe: chunk ci consumed into regs

        if (t == nt - 1) {
            // STS interpolated chunk (both positions) with final rna rounding
#pragma unroll
            for (int j = 0; j < 4; j++) {
                const int idx = tid + j * 256;
                const int kr = idx >> 5, sg = idx & 31;
                float4 r0, r1;
                r0.x = rna_tf32(w0a[j].x); r0.y = rna_tf32(w0a[j].y);
                r0.z = rna_tf32(w0a[j].z); r0.w = rna_tf32(w0a[j].w);
                r1.x = rna_tf32(w1a[j].x); r1.y = rna_tf32(w1a[j].y);
                r1.z = rna_tf32(w1a[j].z); r1.w = rna_tf32(w1a[j].w);
                *reinterpret_cast<float4*>(&sW[kr * 132 + sg * 4])        = r0;
                *reinterpret_cast<float4*>(&sW[4224 + kr * 132 + sg * 4]) = r1;
            }
            __syncthreads();

            // minimal MMA for this k-chunk
#pragma unroll
            for (int ks = 0; ks < 4; ks++) {
                uint32_t aF[2][2][4];
#pragma unroll
                for (int p = 0; p < 2; p++)
#pragma unroll
                    for (int m = 0; m < 2; m++) {
                        const float4 v = *reinterpret_cast<const float4*>(
                            &sAp[(p * 1024 + ((kc * 4 + ks) * 2 + m) * 32 + lane) * 4]);
                        aF[p][m][0] = __float_as_uint(v.x);
                        aF[p][m][1] = __float_as_uint(v.y);
                        aF[p][m][2] = __float_as_uint(v.z);
                        aF[p][m][3] = __float_as_uint(v.w);
                    }
#pragma unroll
                for (int p = 0; p < 2; p++) {
                    const float* Wp = sW + p * 4224;
                    uint32_t bf[2][2];
#pragma unroll
                    for (int n = 0; n < 2; n++) {
                        const int oc = ob + n * 8 + g;
                        bf[n][0] = __float_as_uint(Wp[(ks * 8 + q) * 132 + oc]);
                        bf[n][1] = __float_as_uint(Wp[(ks * 8 + q + 4) * 132 + oc]);
                    }
#pragma unroll
                    for (int m = 0; m < 2; m++)
#pragma unroll
                        for (int n = 0; n < 2; n++)
                            mma_tf32(acc[p][m][n], aF[p][m], bf[n]);
                }
            }
            __syncthreads();   // MMA done before next kc overwrites sW
            kc++; t = 0;
        } else {
            t++;
        }
    }

    // ---- store C[s][pos][b][o] ----
#pragma unroll
    for (int p = 0; p < 2; p++) {
        float* Cb = g_C + ((long)s * 1024 + xr * 32 + 2 * rr + p) * 4096;
#pragma unroll
        for (int m = 0; m < 2; m++)
#pragma unroll
            for (int n = 0; n < 2; n++) {
                const int row = m * 16 + g;
                const int col = ob + n * 8 + q * 2;
                *reinterpret_cast<float2*>(&Cb[row * 128 + col]) =
                    make_float2(acc[p][m][n][0], acc[p][m][n][1]);
                *reinterpret_cast<float2*>(&Cb[(row + 8) * 128 + col]) =
                    make_float2(acc[p][m][n][2], acc[p][m][n][3]);
            }
    }
}

// ---------------------------------------------------------------------------
// K3: idwt + zero-idwt, o-halved. grid (32 xr, 32 b, 2 og), block 256.
// smem 4*32*66*4 = 33792 B -> ~6 CTAs/SM.
// ---------------------------------------------------------------------------
__global__ __launch_bounds__(256) void k_idwt(float* __restrict__ out) {
    __shared__ float sC[4 * 32 * 66];   // [(s*32+y)][o_loc] stride 66
    const int xr = blockIdx.x, b = blockIdx.y, og = blockIdx.z;
    const int tid = threadIdx.x;

    const float4* Cg = reinterpret_cast<const float4*>(g_C);
#pragma unroll
    for (int i = 0; i < 8; i++) {
        const int fid = i * 256 + tid;
        const int row = fid >> 4, c4 = fid & 15;   // row = s*32+y, 16 float4/row
        const int ss = row >> 5, y = row & 31;
        const float4 v = Cg[(((long)ss * 1024 + xr * 32 + y) * 32 + b) * 32
                            + og * 16 + c4];
        float* d = &sC[row * 66 + c4 * 4];
        d[0] = v.x; d[1] = v.y; d[2] = v.z; d[3] = v.w;
    }
    __syncthreads();

    const int y = tid & 31;
    const int t8 = tid >> 5;       // 0..7
    const long ob0 = ((long)b * 128 + og * 64) * 16384 + (4 * xr) * 128 + 4 * y;

#pragma unroll
    for (int j = 0; j < 8; j++) {
        const int ol = t8 * 8 + j;                 // 0..63
        const float ll = sC[(0 * 32 + y) * 66 + ol];
        const float lh = sC[(1 * 32 + y) * 66 + ol];
        const float hl = sC[(2 * 32 + y) * 66 + ol];
        const float hh = sC[(3 * 32 + y) * 66 + ol];
        const float e00 = 0.25f * (ll + lh + hl + hh);
        const float e01 = 0.25f * (ll - lh + hl - hh);
        const float e10 = 0.25f * (ll + lh - hl - hh);
        const float e11 = 0.25f * (ll - lh - hl + hh);
        float* p = out + ob0 + (long)ol * 16384;
        const float4 top = make_float4(e00, e00, e01, e01);
        const float4 bot = make_float4(e10, e10, e11, e11);
        *reinterpret_cast<float4*>(p)       = top;
        *reinterpret_cast<float4*>(p + 128) = top;
        *reinterpret_cast<float4*>(p + 256) = bot;
        *reinterpret_cast<float4*>(p + 384) = bot;
    }
}

// ---------------------------------------------------------------------------
extern "C" void kernel_launch(void* const* d_in, const int* in_sizes, int n_in,
                              void* d_out, int out_size) {
    (void)in_sizes; (void)n_in; (void)out_size;
    const float* x  = (const float*)d_in[0];
    const float* w1 = (const float*)d_in[1];
    const float* w2 = (const float*)d_in[2];
    const float* w3 = (const float*)d_in[3];
    const float* w4 = (const float*)d_in[4];

    cudaFuncSetAttribute(k_gemm, cudaFuncAttributeMaxDynamicSharedMemorySize, KG_SMEM);

    k_dwt  <<<dim3(32, 128), 1024>>>(x);
    k_wprep<<<dim3(8, 128, 4), 256>>>(w1, w2, w3, w4);
    k_gemm <<<dim3(16, 32, 4), 256, KG_SMEM>>>();
    k_idwt <<<dim3(32, 32, 2), 256>>>((float*)d_out);
}

// round 7
// speedup vs baseline: 2.3631x; 1.1529x over previous
#include <cuda_runtime.h>
#include <cstdint>

// ---------------------------------------------------------------------------
// FlexibleWaveConv2d, round 7.
//   K1a k_dwt   : x -> A[s][pos][k][b]           (4x4 block Haar, tf32-rna)
//   K1b k_wprep : w_s -> Wt[s][uv][k][o]         (transpose, tf32-rna)
//   K2  k_gemm  : 2x2 position tiles chosen so ALL 4 positions share the SAME
//                 <=4 tap matrices (pairs (2k+1,2k+2) share taps {k,k+1}).
//                 Stream the 4 tap k-chunks once (cp.async double buffer),
//                 interpolate 4 position-W chunks, minimal tf32 MMA.
//   K3  k_idwt  : C -> out, o-halved blocks, coalesced.
// ---------------------------------------------------------------------------

#define S_A   (1024L*128*32)
#define N_A   (4L*1024*128*32)
#define N_WT  (4L*256*128*128)
#define N_C   (4L*1024*32*128)

static __device__ float g_A [N_A];   // [s][pos][k][b]
static __device__ float g_Wt[N_WT];  // [s][u*16+v][k][o]
static __device__ float g_C [N_C];   // [s][pos][b][o]

__device__ __forceinline__ float rna_tf32(float x) {
    float r;
    asm("cvt.rna.tf32.f32 %0, %1;" : "=f"(r) : "f"(x));
    return r;
}

// ---------------------------------------------------------------------------
// K1a: 4x4 block Haar. grid (32 x-rows, 128 channels), block 1024.
// ---------------------------------------------------------------------------
__global__ __launch_bounds__(1024) void k_dwt(const float* __restrict__ x) {
    const int xr = blockIdx.x;
    const int ci = blockIdx.y;
    __shared__ float vals[4][32][33];

    const int tid = threadIdx.x;
    {
        const int b = tid >> 5, y = tid & 31;
        const float4* px = reinterpret_cast<const float4*>(x)
                         + ((long)(b * 128 + ci) * 128 + 4 * xr) * 32 + y;
        float4 r0 = px[0], r1 = px[32], r2 = px[64], r3 = px[96];
        float q00 = r0.x + r0.y + r1.x + r1.y;
        float q01 = r0.z + r0.w + r1.z + r1.w;
        float q10 = r2.x + r2.y + r3.x + r3.y;
        float q11 = r2.z + r2.w + r3.z + r3.w;
        vals[0][y][b] = rna_tf32(0.25f * (q00 + q01 + q10 + q11));
        vals[1][y][b] = rna_tf32(0.25f * (q00 - q01 + q10 - q11));
        vals[2][y][b] = rna_tf32(0.25f * (q00 + q01 - q10 - q11));
        vals[3][y][b] = rna_tf32(0.25f * (q00 - q01 - q10 + q11));
    }
    __syncthreads();
    {
        const int y2 = tid >> 5, b2 = tid & 31;
        const long base = ((long)(xr * 32 + y2) * 128 + ci) * 32 + b2;
        g_A[0 * S_A + base] = vals[0][y2][b2];
        g_A[1 * S_A + base] = vals[1][y2][b2];
        g_A[2 * S_A + base] = vals[2][y2][b2];
        g_A[3 * S_A + base] = vals[3][y2][b2];
    }
}

// ---------------------------------------------------------------------------
// K1b: weight transpose (i,o,u,v) -> [s][uv][k][o], tf32-rna.
// ---------------------------------------------------------------------------
__global__ __launch_bounds__(256) void k_wprep(const float* __restrict__ w0,
                                               const float* __restrict__ w1,
                                               const float* __restrict__ w2,
                                               const float* __restrict__ w3) {
    const int uvb = blockIdx.x, k = blockIdx.y, s = blockIdx.z;
    const float* w = (s == 0) ? w0 : (s == 1) ? w1 : (s == 2) ? w2 : w3;
    __shared__ float t[128][33];
    const int tid = threadIdx.x;
    const int uvl = tid & 31;
    const int uv0 = uvb * 32;
    for (int o = tid >> 5; o < 128; o += 8)
        t[o][uvl] = w[((long)k * 128 + o) * 256 + uv0 + uvl];
    __syncthreads();
    const int o = tid & 127;
    for (int j = tid >> 7; j < 32; j += 2)
        g_Wt[(((long)s * 256 + uv0 + j) * 128 + k) * 128 + o] = rna_tf32(t[o][j]);
}

// ---------------------------------------------------------------------------
// K2: tap-shared 2x2 tile GEMM.
// grid (17 gy, 17 gx, 4 s), block 512 (16 warps), 1 CTA/SM.
// Groups: g=0 -> {0} tap {0}; g=1..15 -> {2g-1,2g} taps {g-1,g}; g=16 -> {31} tap {15}.
// smem floats:
//   sAp  [0,16384)      : 4 pos x 1024 float4, fragment-packed A
//   sTap [16384,34816)  : rawA scratch (4x4608) / tap double buf (2 x 4 x 2176)
//   sW   [34816,43520)  : 4 pos x 2176 interpolated W chunk (k=16, stride 136)
// ---------------------------------------------------------------------------
#define KG_FL   (16384 + 18432 + 8704)
#define KG_SMEM (KG_FL * 4)

__device__ __forceinline__ void mma_tf32(float acc[4], const uint32_t a[4],
                                         const uint32_t b[2]) {
    asm volatile(
        "mma.sync.aligned.m16n8k8.row.col.f32.tf32.tf32.f32 "
        "{%0,%1,%2,%3}, {%4,%5,%6,%7}, {%8,%9}, {%0,%1,%2,%3};\n"
        : "+f"(acc[0]), "+f"(acc[1]), "+f"(acc[2]), "+f"(acc[3])
        : "r"(a[0]), "r"(a[1]), "r"(a[2]), "r"(a[3]), "r"(b[0]), "r"(b[1]));
}

__device__ __forceinline__ void cpasync16(uint32_t dst, const void* src) {
    asm volatile("cp.async.cg.shared.global [%0], [%1], 16;"
                 :: "r"(dst), "l"(src));
}

__device__ __forceinline__ void group_meta(int g, int& start, int& np, int& t0,
                                           float c[2][2]) {
    if (g == 0)       { start = 0;  np = 1; t0 = 0;
                        c[0][0] = 1.0f;  c[0][1] = 0.0f; c[1][0] = 0.0f; c[1][1] = 0.0f; }
    else if (g == 16) { start = 31; np = 1; t0 = 15;
                        c[0][0] = 1.0f;  c[0][1] = 0.0f; c[1][0] = 0.0f; c[1][1] = 0.0f; }
    else              { start = 2 * g - 1; np = 2; t0 = g - 1;
                        c[0][0] = 0.75f; c[0][1] = 0.25f;
                        c[1][0] = 0.25f; c[1][1] = 0.75f; }
}

__global__ __launch_bounds__(512, 1) void k_gemm() {
    extern __shared__ float sm[];
    float* sAp  = sm;
    float* sTap = sm + 16384;
    float* sW   = sm + 34816;

    const int gy = blockIdx.x, gx = blockIdx.y, s = blockIdx.z;
    const int tid = threadIdx.x;

    int xs, npx, u0; float cux[2][2];
    int ys, npy, v0; float cvy[2][2];
    group_meta(gx, xs, npx, u0, cux);
    group_meta(gy, ys, npy, v0, cvy);

    int posi[4];
    const float* Tp[4];
    float cc[4][4];
#pragma unroll
    for (int ix = 0; ix < 2; ix++)
#pragma unroll
        for (int iy = 0; iy < 2; iy++) {
            const int p = ix * 2 + iy;
            posi[p] = (xs + (ix < npx ? ix : npx - 1)) * 32
                    + (ys + (iy < npy ? iy : npy - 1));
        }
#pragma unroll
    for (int iu = 0; iu < 2; iu++)
#pragma unroll
        for (int iv = 0; iv < 2; iv++) {
            const int t = iu * 2 + iv;
            const int uu = u0 + (iu < npx ? iu : npx - 1);
            const int vv = v0 + (iv < npy ? iv : npy - 1);
            Tp[t] = g_Wt + ((long)s * 256 + uu * 16 + vv) * 16384;
#pragma unroll
            for (int ix = 0; ix < 2; ix++)
#pragma unroll
                for (int iy = 0; iy < 2; iy++)
                    cc[ix * 2 + iy][t] = cux[ix][iu] * cvy[iy][iv];
        }

    // ---- stage raw A (4 positions) into sTap scratch, stride 36 ----
#pragma unroll
    for (int j = 0; j < 8; j++) {
        const int idx = tid + j * 512;           // float4 id over 4096
        const int p = idx >> 10, li = idx & 1023;
        const int k = li >> 3, b4 = (li & 7) << 2;
        cpasync16((uint32_t)__cvta_generic_to_shared(sTap + p * 4608 + k * 36 + b4),
                  g_A + ((long)s * 1024 + posi[p]) * 4096 + li * 4);
    }
    asm volatile("cp.async.commit_group;");
    asm volatile("cp.async.wait_group 0;");
    __syncthreads();

    // ---- repack A into fragment order ----
    {
        float4 tmp[8];
#pragma unroll
        for (int i = 0; i < 8; i++) {
            const int fid = i * 512 + tid;
            const int p = fid >> 10, r = fid & 1023;
            const int k8 = r >> 6, m = (r >> 5) & 1, lane = r & 31;
            const int g = lane >> 2, q = lane & 3;
            const float* rb = sTap + p * 4608;
            tmp[i].x = rb[(8 * k8 + q) * 36 + 16 * m + g];
            tmp[i].y = rb[(8 * k8 + q) * 36 + 16 * m + 8 + g];
            tmp[i].z = rb[(8 * k8 + q + 4) * 36 + 16 * m + g];
            tmp[i].w = rb[(8 * k8 + q + 4) * 36 + 16 * m + 8 + g];
        }
#pragma unroll
        for (int i = 0; i < 8; i++)
            *reinterpret_cast<float4*>(&sAp[(i * 512 + tid) * 4]) = tmp[i];
    }
    __syncthreads();          // sAp ready; sTap free for tap buffers

    const int warp = tid >> 5, lane = tid & 31;
    const int g = lane >> 2, q = lane & 3;
    const int ob = warp << 3;                 // 8 o-cols per warp

    float acc[4][2][4];
#pragma unroll
    for (int p = 0; p < 4; p++)
#pragma unroll
        for (int m = 0; m < 2; m++)
#pragma unroll
            for (int i = 0; i < 4; i++) acc[p][m][i] = 0.0f;

    // tap chunk group: 4 taps x 16k x 128o, dst stride 136
    auto issue = [&](int kc) {
        float* dst = sTap + (kc & 1) * 8704;
#pragma unroll
        for (int j = 0; j < 4; j++) {
            const int gidx = tid + j * 512;       // float4 id over 2048
            const int t = gidx >> 9, li = gidx & 511;
            const int kr = li >> 5, sg = li & 31;
            cpasync16((uint32_t)__cvta_generic_to_shared(
                          dst + t * 2176 + kr * 136 + sg * 4),
                      Tp[t] + kc * 2048 + li * 4);
        }
        asm volatile("cp.async.commit_group;");
    };

    issue(0);
    issue(1);

    const int ikr = tid >> 5, isg = tid & 31;
    const int ioff = ikr * 136 + isg * 4;

    for (int kc = 0; kc < 8; kc++) {
        if (kc < 7) asm volatile("cp.async.wait_group 1;");
        else        asm volatile("cp.async.wait_group 0;");
        __syncthreads();      // tap buf visible to all; prev MMA done (sW free)

        // ---- interp: 4 taps -> 4 positions' W chunk ----
        {
            const float* tb = sTap + (kc & 1) * 8704;
            const float4 t0 = *reinterpret_cast<const float4*>(tb + ioff);
            const float4 t1 = *reinterpret_cast<const float4*>(tb + 2176 + ioff);
            const float4 t2 = *reinterpret_cast<const float4*>(tb + 4352 + ioff);
            const float4 t3 = *reinterpret_cast<const float4*>(tb + 6528 + ioff);
#pragma unroll
            for (int p = 0; p < 4; p++) {
                float4 w;
                w.x = cc[p][0]*t0.x + cc[p][1]*t1.x + cc[p][2]*t2.x + cc[p][3]*t3.x;
                w.y = cc[p][0]*t0.y + cc[p][1]*t1.y + cc[p][2]*t2.y + cc[p][3]*t3.y;
                w.z = cc[p][0]*t0.z + cc[p][1]*t1.z + cc[p][2]*t2.z + cc[p][3]*t3.z;
                w.w = cc[p][0]*t0.w + cc[p][1]*t1.w + cc[p][2]*t2.w + cc[p][3]*t3.w;
                w.x = rna_tf32(w.x); w.y = rna_tf32(w.y);
                w.z = rna_tf32(w.z); w.w = rna_tf32(w.w);
                *reinterpret_cast<float4*>(sW + p * 2176 + ioff) = w;
            }
        }
        if (kc + 2 < 8) issue(kc + 2);
        __syncthreads();      // sW ready

        // ---- minimal MMA for this k-chunk ----
#pragma unroll
        for (int ks = 0; ks < 2; ks++) {
            const int k8 = kc * 2 + ks;
            uint32_t aF[4][2][4];
#pragma unroll
            for (int p = 0; p < 4; p++)
#pragma unroll
                for (int m = 0; m < 2; m++) {
                    const float4 v = *reinterpret_cast<const float4*>(
                        &sAp[(p * 1024 + (k8 * 2 + m) * 32 + lane) * 4]);
                    aF[p][m][0] = __float_as_uint(v.x);
                    aF[p][m][1] = __float_as_uint(v.y);
                    aF[p][m][2] = __float_as_uint(v.z);
                    aF[p][m][3] = __float_as_uint(v.w);
                }
#pragma unroll
            for (int p = 0; p < 4; p++) {
                uint32_t bf[2];
                bf[0] = __float_as_uint(sW[p * 2176 + (8 * ks + q) * 136 + ob + g]);
                bf[1] = __float_as_uint(sW[p * 2176 + (8 * ks + q + 4) * 136 + ob + g]);
#pragma unroll
                for (int m = 0; m < 2; m++)
                    mma_tf32(acc[p][m], aF[p][m], bf);
            }
        }
    }

    // ---- store C (valid positions only) ----
#pragma unroll
    for (int p = 0; p < 4; p++) {
        const int ix = p >> 1, iy = p & 1;
        if (ix >= npx || iy >= npy) continue;
        float* Cb = g_C + ((long)s * 1024 + posi[p]) * 4096;
#pragma unroll
        for (int m = 0; m < 2; m++) {
            const int row = m * 16 + g;
            const int col = ob + q * 2;
            *reinterpret_cast<float2*>(&Cb[row * 128 + col]) =
                make_float2(acc[p][m][0], acc[p][m][1]);
            *reinterpret_cast<float2*>(&Cb[(row + 8) * 128 + col]) =
                make_float2(acc[p][m][2], acc[p][m][3]);
        }
    }
}

// ---------------------------------------------------------------------------
// K3: idwt + zero-idwt, o-halved. grid (32 xr, 32 b, 2 og), block 256.
// ---------------------------------------------------------------------------
__global__ __launch_bounds__(256) void k_idwt(float* __restrict__ out) {
    __shared__ float sC[4 * 32 * 66];
    const int xr = blockIdx.x, b = blockIdx.y, og = blockIdx.z;
    const int tid = threadIdx.x;

    const float4* Cg = reinterpret_cast<const float4*>(g_C);
#pragma unroll
    for (int i = 0; i < 8; i++) {
        const int fid = i * 256 + tid;
        const int row = fid >> 4, c4 = fid & 15;
        const int ss = row >> 5, y = row & 31;
        const float4 v = Cg[(((long)ss * 1024 + xr * 32 + y) * 32 + b) * 32
                            + og * 16 + c4];
        float* d = &sC[row * 66 + c4 * 4];
        d[0] = v.x; d[1] = v.y; d[2] = v.z; d[3] = v.w;
    }
    __syncthreads();

    const int y = tid & 31;
    const int t8 = tid >> 5;
    const long ob0 = ((long)b * 128 + og * 64) * 16384 + (4 * xr) * 128 + 4 * y;

#pragma unroll
    for (int j = 0; j < 8; j++) {
        const int ol = t8 * 8 + j;
        const float ll = sC[(0 * 32 + y) * 66 + ol];
        const float lh = sC[(1 * 32 + y) * 66 + ol];
        const float hl = sC[(2 * 32 + y) * 66 + ol];
        const float hh = sC[(3 * 32 + y) * 66 + ol];
        const float e00 = 0.25f * (ll + lh + hl + hh);
        const float e01 = 0.25f * (ll - lh + hl - hh);
        const float e10 = 0.25f * (ll + lh - hl - hh);
        const float e11 = 0.25f * (ll - lh - hl + hh);
        float* p = out + ob0 + (long)ol * 16384;
        const float4 top = make_float4(e00, e00, e01, e01);
        const float4 bot = make_float4(e10, e10, e11, e11);
        *reinterpret_cast<float4*>(p)       = top;
        *reinterpret_cast<float4*>(p + 128) = top;
        *reinterpret_cast<float4*>(p + 256) = bot;
        *reinterpret_cast<float4*>(p + 384) = bot;
    }
}

// ---------------------------------------------------------------------------
extern "C" void kernel_launch(void* const* d_in, const int* in_sizes, int n_in,
                              void* d_out, int out_size) {
    (void)in_sizes; (void)n_in; (void)out_size;
    const float* x  = (const float*)d_in[0];
    const float* w1 = (const float*)d_in[1];
    const float* w2 = (const float*)d_in[2];
    const float* w3 = (const float*)d_in[3];
    const float* w4 = (const float*)d_in[4];

    cudaFuncSetAttribute(k_gemm, cudaFuncAttributeMaxDynamicSharedMemorySize, KG_SMEM);

    k_dwt  <<<dim3(32, 128), 1024>>>(x);
    k_wprep<<<dim3(8, 128, 4), 256>>>(w1, w2, w3, w4);
    k_gemm <<<dim3(17, 17, 4), 512, KG_SMEM>>>();
    k_idwt <<<dim3(32, 32, 2), 256>>>((float*)d_out);
}

// round 9
// speedup vs baseline: 2.8740x; 1.2162x over previous
#include <cuda_runtime.h>
#include <cstdint>

// ---------------------------------------------------------------------------
// FlexibleWaveConv2d, round 9 (= round 8 resubmitted after infra failure).
//   K1a k_dwt   : x -> A[s][pos][k][b]           (4x4 block Haar, tf32-rna)
//   K1b k_wprep : w_s -> Wt[s][uv][k][o]         (transpose, tf32-rna)
//   K2  k_gemm  : 2x2 tap-shared position tiles; 256-thread blocks, 2 CTAs/SM.
//                 Tap chunks (8k x 128o x 4 taps) streamed via 2-deep cp.async;
//                 B-fragments interpolated IN REGISTERS (no sW smem stage);
//                 minimal tf32 mma.sync m16n8k8.
//   K3  k_idwt  : C -> out, 512-thread blocks (2 batch each), 3 CTAs/SM.
// ---------------------------------------------------------------------------

#define S_A   (1024L*128*32)
#define N_A   (4L*1024*128*32)
#define N_WT  (4L*256*128*128)
#define N_C   (4L*1024*32*128)

static __device__ float g_A [N_A];   // [s][pos][k][b]
static __device__ float g_Wt[N_WT];  // [s][u*16+v][k][o]
static __device__ float g_C [N_C];   // [s][pos][b][o]

__device__ __forceinline__ float rna_tf32(float x) {
    float r;
    asm("cvt.rna.tf32.f32 %0, %1;" : "=f"(r) : "f"(x));
    return r;
}

// ---------------------------------------------------------------------------
// K1a: 4x4 block Haar. grid (32 x-rows, 128 channels), block 1024.
// ---------------------------------------------------------------------------
__global__ __launch_bounds__(1024) void k_dwt(const float* __restrict__ x) {
    const int xr = blockIdx.x;
    const int ci = blockIdx.y;
    __shared__ float vals[4][32][33];

    const int tid = threadIdx.x;
    {
        const int b = tid >> 5, y = tid & 31;
        const float4* px = reinterpret_cast<const float4*>(x)
                         + ((long)(b * 128 + ci) * 128 + 4 * xr) * 32 + y;
        float4 r0 = px[0], r1 = px[32], r2 = px[64], r3 = px[96];
        float q00 = r0.x + r0.y + r1.x + r1.y;
        float q01 = r0.z + r0.w + r1.z + r1.w;
        float q10 = r2.x + r2.y + r3.x + r3.y;
        float q11 = r2.z + r2.w + r3.z + r3.w;
        vals[0][y][b] = rna_tf32(0.25f * (q00 + q01 + q10 + q11));
        vals[1][y][b] = rna_tf32(0.25f * (q00 - q01 + q10 - q11));
        vals[2][y][b] = rna_tf32(0.25f * (q00 + q01 - q10 - q11));
        vals[3][y][b] = rna_tf32(0.25f * (q00 - q01 - q10 + q11));
    }
    __syncthreads();
    {
        const int y2 = tid >> 5, b2 = tid & 31;
        const long base = ((long)(xr * 32 + y2) * 128 + ci) * 32 + b2;
        g_A[0 * S_A + base] = vals[0][y2][b2];
        g_A[1 * S_A + base] = vals[1][y2][b2];
        g_A[2 * S_A + base] = vals[2][y2][b2];
        g_A[3 * S_A + base] = vals[3][y2][b2];
    }
}

// ---------------------------------------------------------------------------
// K1b: weight transpose (i,o,u,v) -> [s][uv][k][o], tf32-rna.
// ---------------------------------------------------------------------------
__global__ __launch_bounds__(256) void k_wprep(const float* __restrict__ w0,
                                               const float* __restrict__ w1,
                                               const float* __restrict__ w2,
                                               const float* __restrict__ w3) {
    const int uvb = blockIdx.x, k = blockIdx.y, s = blockIdx.z;
    const float* w = (s == 0) ? w0 : (s == 1) ? w1 : (s == 2) ? w2 : w3;
    __shared__ float t[128][33];
    const int tid = threadIdx.x;
    const int uvl = tid & 31;
    const int uv0 = uvb * 32;
    for (int o = tid >> 5; o < 128; o += 8)
        t[o][uvl] = w[((long)k * 128 + o) * 256 + uv0 + uvl];
    __syncthreads();
    const int o = tid & 127;
    for (int j = tid >> 7; j < 32; j += 2)
        g_Wt[(((long)s * 256 + uv0 + j) * 128 + k) * 128 + o] = rna_tf32(t[o][j]);
}

// ---------------------------------------------------------------------------
// K2: tap-shared 2x2 tile GEMM, register B-fragments, 2 CTAs/SM.
// grid (17 gy, 17 gx, 4 s), block 256 (8 warps).
// smem floats:
//   sAp [0,16384)      : 4 pos x 1024 float4, fragment-packed A
//   sR  [16384,25600)  : rawA half-stage (2x4608) / tap ring (2 x 4 x 1088)
// ---------------------------------------------------------------------------
#define KG_FL   (16384 + 9216 + 32)
#define KG_SMEM (KG_FL * 4)

__device__ __forceinline__ void mma_tf32(float acc[4], const uint32_t a[4],
                                         const uint32_t b[2]) {
    asm volatile(
        "mma.sync.aligned.m16n8k8.row.col.f32.tf32.tf32.f32 "
        "{%0,%1,%2,%3}, {%4,%5,%6,%7}, {%8,%9}, {%0,%1,%2,%3};\n"
        : "+f"(acc[0]), "+f"(acc[1]), "+f"(acc[2]), "+f"(acc[3])
        : "r"(a[0]), "r"(a[1]), "r"(a[2]), "r"(a[3]), "r"(b[0]), "r"(b[1]));
}

__device__ __forceinline__ void cpasync16(uint32_t dst, const void* src) {
    asm volatile("cp.async.cg.shared.global [%0], [%1], 16;"
                 :: "r"(dst), "l"(src));
}

__device__ __forceinline__ void group_meta(int g, int& start, int& np,
                                           int& t0, float c[2][2]) {
    if (g == 0)       { start = 0;  np = 1; t0 = 0;
                        c[0][0] = 1.0f;  c[0][1] = 0.0f; c[1][0] = 0.0f; c[1][1] = 0.0f; }
    else if (g == 16) { start = 31; np = 1; t0 = 15;
                        c[0][0] = 1.0f;  c[0][1] = 0.0f; c[1][0] = 0.0f; c[1][1] = 0.0f; }
    else              { start = 2 * g - 1; np = 2; t0 = g - 1;
                        c[0][0] = 0.75f; c[0][1] = 0.25f;
                        c[1][0] = 0.25f; c[1][1] = 0.75f; }
}

__global__ __launch_bounds__(256, 2) void k_gemm() {
    extern __shared__ float sm[];
    float* sAp = sm;            // 16384 floats
    float* sR  = sm + 16384;    // 9216 floats

    const int gy = blockIdx.x, gx = blockIdx.y, s = blockIdx.z;
    const int tid = threadIdx.x;

    int xs, npx, u0; float cux[2][2];
    int ys, npy, v0; float cvy[2][2];
    group_meta(gx, xs, npx, u0, cux);
    group_meta(gy, ys, npy, v0, cvy);

    int posi[4];
    const float* Tp[4];
#pragma unroll
    for (int ix = 0; ix < 2; ix++)
#pragma unroll
        for (int iy = 0; iy < 2; iy++)
            posi[ix * 2 + iy] = (xs + (ix < npx ? ix : npx - 1)) * 32
                              + (ys + (iy < npy ? iy : npy - 1));
#pragma unroll
    for (int iu = 0; iu < 2; iu++)
#pragma unroll
        for (int iv = 0; iv < 2; iv++) {
            const int uu = u0 + (iu < npx ? iu : npx - 1);
            const int vv = v0 + (iv < npy ? iv : npy - 1);
            Tp[iu * 2 + iv] = g_Wt + ((long)s * 256 + uu * 16 + vv) * 16384;
        }

    // ---- prologue: stage + repack A in 2 halves (2 positions each) ----
#pragma unroll
    for (int ph = 0; ph < 2; ph++) {
#pragma unroll
        for (int j = 0; j < 8; j++) {
            const int idx = tid + j * 256;        // 0..2047 float4
            const int pl = idx >> 10, li = idx & 1023;
            const int k = li >> 3, b4 = (li & 7) << 2;
            cpasync16((uint32_t)__cvta_generic_to_shared(
                          sR + pl * 4608 + k * 36 + b4),
                      g_A + ((long)s * 1024 + posi[ph * 2 + pl]) * 4096 + li * 4);
        }
        asm volatile("cp.async.commit_group;");
        asm volatile("cp.async.wait_group 0;");
        __syncthreads();
        float4 tmp[8];
#pragma unroll
        for (int i = 0; i < 8; i++) {
            const int fid = i * 256 + tid;        // 0..2047 frags
            const int pl = fid >> 10, r = fid & 1023;
            const int k8 = r >> 6, m = (r >> 5) & 1, lane = r & 31;
            const int gg = lane >> 2, qq = lane & 3;
            const float* rb = sR + pl * 4608;
            tmp[i].x = rb[(8 * k8 + qq) * 36 + 16 * m + gg];
            tmp[i].y = rb[(8 * k8 + qq) * 36 + 16 * m + 8 + gg];
            tmp[i].z = rb[(8 * k8 + qq + 4) * 36 + 16 * m + gg];
            tmp[i].w = rb[(8 * k8 + qq + 4) * 36 + 16 * m + 8 + gg];
        }
#pragma unroll
        for (int i = 0; i < 8; i++) {
            const int fid = i * 256 + tid;
            const int pl = fid >> 10, r = fid & 1023;
            *reinterpret_cast<float4*>(&sAp[((ph * 2 + pl) * 1024 + r) * 4]) = tmp[i];
        }
        __syncthreads();      // repack reads done before next stage overwrites sR
    }

    const int warp = tid >> 5, lane = tid & 31;
    const int g = lane >> 2, q = lane & 3;
    const int ob = warp << 4;                 // 16 o-cols per warp

    float acc[4][2][2][4];                    // [p][m][n][4]
#pragma unroll
    for (int p = 0; p < 4; p++)
#pragma unroll
        for (int m = 0; m < 2; m++)
#pragma unroll
            for (int n = 0; n < 2; n++)
#pragma unroll
                for (int i = 0; i < 4; i++) acc[p][m][n][i] = 0.0f;

    // tap chunk: 4 taps x 8k x 128o, ring of 2, dst row-stride 136 (conflict-free)
    auto issue = [&](int kc) {
        float* dst = sR + (kc & 1) * 4352;
        const int kr = tid >> 5, og = tid & 31;
#pragma unroll
        for (int j = 0; j < 4; j++)
            cpasync16((uint32_t)__cvta_generic_to_shared(
                          dst + j * 1088 + kr * 136 + og * 4),
                      Tp[j] + kc * 1024 + tid * 4);
        asm volatile("cp.async.commit_group;");
    };

    issue(0);
    issue(1);

    for (int kc = 0; kc < 16; kc++) {
        if (kc < 15) asm volatile("cp.async.wait_group 1;");
        else         asm volatile("cp.async.wait_group 0;");
        __syncthreads();      // chunk kc visible to all

        // ---- interpolate B-fragments in registers ----
        const float* tb = sR + (kc & 1) * 4352;
        float bfv[4][2][2];   // [p][n][kk]
#pragma unroll
        for (int kk = 0; kk < 2; kk++)
#pragma unroll
            for (int n = 0; n < 2; n++) {
                const int koff = (q + 4 * kk) * 136 + ob + n * 8 + g;
                const float t00 = tb[koff];              // (u0,v0)
                const float t01 = tb[1088 + koff];       // (u0,v1)
                const float t10 = tb[2176 + koff];       // (u1,v0)
                const float t11 = tb[3264 + koff];       // (u1,v1)
#pragma unroll
                for (int iy = 0; iy < 2; iy++) {
                    const float m0 = cvy[iy][0] * t00 + cvy[iy][1] * t01;
                    const float m1 = cvy[iy][0] * t10 + cvy[iy][1] * t11;
#pragma unroll
                    for (int ix = 0; ix < 2; ix++)
                        bfv[ix * 2 + iy][n][kk] =
                            rna_tf32(cux[ix][0] * m0 + cux[ix][1] * m1);
                }
            }
        __syncthreads();      // all tap reads done before ring slot reuse
        if (kc + 2 < 16) issue(kc + 2);

        // ---- minimal MMA ----
#pragma unroll
        for (int p = 0; p < 4; p++) {
            uint32_t bf[2][2];
#pragma unroll
            for (int n = 0; n < 2; n++) {
                bf[n][0] = __float_as_uint(bfv[p][n][0]);
                bf[n][1] = __float_as_uint(bfv[p][n][1]);
            }
#pragma unroll
            for (int m = 0; m < 2; m++) {
                const float4 v = *reinterpret_cast<const float4*>(
                    &sAp[(p * 1024 + (kc * 2 + m) * 32 + lane) * 4]);
                uint32_t af[4];
                af[0] = __float_as_uint(v.x);
                af[1] = __float_as_uint(v.y);
                af[2] = __float_as_uint(v.z);
                af[3] = __float_as_uint(v.w);
#pragma unroll
                for (int n = 0; n < 2; n++)
                    mma_tf32(acc[p][m][n], af, bf[n]);
            }
        }
    }

    // ---- store C (valid positions only) ----
#pragma unroll
    for (int p = 0; p < 4; p++) {
        const int ix = p >> 1, iy = p & 1;
        if (ix >= npx || iy >= npy) continue;
        float* Cb = g_C + ((long)s * 1024 + posi[p]) * 4096;
#pragma unroll
        for (int m = 0; m < 2; m++)
#pragma unroll
            for (int n = 0; n < 2; n++) {
                const int row = m * 16 + g;
                const int col = ob + n * 8 + q * 2;
                *reinterpret_cast<float2*>(&Cb[row * 128 + col]) =
                    make_float2(acc[p][m][n][0], acc[p][m][n][1]);
                *reinterpret_cast<float2*>(&Cb[(row + 8) * 128 + col]) =
                    make_float2(acc[p][m][n][2], acc[p][m][n][3]);
            }
    }
}

// ---------------------------------------------------------------------------
// K3: idwt + zero-idwt. grid (32 xr, 16 bb, 2 og), block 512 (2 b each).
// dyn smem 2*8448*4 = 67584 B -> 3 CTAs/SM.
// ---------------------------------------------------------------------------
#define K3_SMEM (2 * 8448 * 4)

__global__ __launch_bounds__(512, 3) void k_idwt(float* __restrict__ out) {
    extern __shared__ float sC[];   // [hb][(s*32+y)][o_loc] stride 66
    const int xr = blockIdx.x, bb = blockIdx.y, og = blockIdx.z;
    const int tid = threadIdx.x;
    const int hb = tid >> 8, lt = tid & 255;
    const int b = bb * 2 + hb;
    float* sB = sC + hb * 8448;

    const float4* Cg = reinterpret_cast<const float4*>(g_C);
#pragma unroll
    for (int i = 0; i < 8; i++) {
        const int fid = i * 256 + lt;
        const int row = fid >> 4, c4 = fid & 15;
        const int ss = row >> 5, y = row & 31;
        const float4 v = Cg[(((long)ss * 1024 + xr * 32 + y) * 32 + b) * 32
                            + og * 16 + c4];
        float* d = &sB[row * 66 + c4 * 4];
        d[0] = v.x; d[1] = v.y; d[2] = v.z; d[3] = v.w;
    }
    __syncthreads();

    const int y = lt & 31;
    const int t8 = lt >> 5;
    const long ob0 = ((long)b * 128 + og * 64) * 16384 + (4 * xr) * 128 + 4 * y;

#pragma unroll
    for (int j = 0; j < 8; j++) {
        const int ol = t8 * 8 + j;
        const float ll = sB[(0 * 32 + y) * 66 + ol];
        const float lh = sB[(1 * 32 + y) * 66 + ol];
        const float hl = sB[(2 * 32 + y) * 66 + ol];
        const float hh = sB[(3 * 32 + y) * 66 + ol];
        const float e00 = 0.25f * (ll + lh + hl + hh);
        const float e01 = 0.25f * (ll - lh + hl - hh);
        const float e10 = 0.25f * (ll + lh - hl - hh);
        const float e11 = 0.25f * (ll - lh - hl + hh);
        float* p = out + ob0 + (long)ol * 16384;
        const float4 top = make_float4(e00, e00, e01, e01);
        const float4 bot = make_float4(e10, e10, e11, e11);
        *reinterpret_cast<float4*>(p)       = top;
        *reinterpret_cast<float4*>(p + 128) = top;
        *reinterpret_cast<float4*>(p + 256) = bot;
        *reinterpret_cast<float4*>(p + 384) = bot;
    }
}

// ---------------------------------------------------------------------------
extern "C" void kernel_launch(void* const* d_in, const int* in_sizes, int n_in,
                              void* d_out, int out_size) {
    (void)in_sizes; (void)n_in; (void)out_size;
    const float* x  = (const float*)d_in[0];
    const float* w1 = (const float*)d_in[1];
    const float* w2 = (const float*)d_in[2];
    const float* w3 = (const float*)d_in[3];
    const float* w4 = (const float*)d_in[4];

    cudaFuncSetAttribute(k_gemm, cudaFuncAttributeMaxDynamicSharedMemorySize, KG_SMEM);
    cudaFuncSetAttribute(k_idwt, cudaFuncAttributeMaxDynamicSharedMemorySize, K3_SMEM);

    k_dwt  <<<dim3(32, 128), 1024>>>(x);
    k_wprep<<<dim3(8, 128, 4), 256>>>(w1, w2, w3, w4);
    k_gemm <<<dim3(17, 17, 4), 256, KG_SMEM>>>();
    k_idwt <<<dim3(32, 16, 2), 512, K3_SMEM>>>((float*)d_out);
}

// round 12
// speedup vs baseline: 3.0033x; 1.0450x over previous
#include <cuda_runtime.h>
#include <cstdint>

// ---------------------------------------------------------------------------
// FlexibleWaveConv2d, round 10.
//   K1a k_dwt   : x -> A[s][pos][k][b]           (4x4 block Haar, tf32-rna)
//   K1b k_wprep : w_s -> Wt[s][uv][k][o]         (block-per-(k,s) transpose)
//   K2  k_gemm  : 2x2 tap-shared position tiles; BARRIER-FREE mainloop:
//                 taps fetched per-thread via LDG (register double buffer),
//                 B-fragments interpolated in registers, minimal tf32 MMA.
//   K3  k_idwt  : C -> out, 512-thread blocks (2 batch each), 3 CTAs/SM.
// ---------------------------------------------------------------------------

#define S_A   (1024L*128*32)
#define N_A   (4L*1024*128*32)
#define N_WT  (4L*256*128*128)
#define N_C   (4L*1024*32*128)

static __device__ float g_A [N_A];   // [s][pos][k][b]
static __device__ float g_Wt[N_WT];  // [s][u*16+v][k][o]
static __device__ float g_C [N_C];   // [s][pos][b][o]

__device__ __forceinline__ float rna_tf32(float x) {
    float r;
    asm("cvt.rna.tf32.f32 %0, %1;" : "=f"(r) : "f"(x));
    return r;
}

// ---------------------------------------------------------------------------
// K1a: 4x4 block Haar. grid (32 x-rows, 128 channels), block 1024.
// ---------------------------------------------------------------------------
__global__ __launch_bounds__(1024) void k_dwt(const float* __restrict__ x) {
    const int xr = blockIdx.x;
    const int ci = blockIdx.y;
    __shared__ float vals[4][32][33];

    const int tid = threadIdx.x;
    {
        const int b = tid >> 5, y = tid & 31;
        const float4* px = reinterpret_cast<const float4*>(x)
                         + ((long)(b * 128 + ci) * 128 + 4 * xr) * 32 + y;
        float4 r0 = px[0], r1 = px[32], r2 = px[64], r3 = px[96];
        float q00 = r0.x + r0.y + r1.x + r1.y;
        float q01 = r0.z + r0.w + r1.z + r1.w;
        float q10 = r2.x + r2.y + r3.x + r3.y;
        float q11 = r2.z + r2.w + r3.z + r3.w;
        vals[0][y][b] = rna_tf32(0.25f * (q00 + q01 + q10 + q11));
        vals[1][y][b] = rna_tf32(0.25f * (q00 - q01 + q10 - q11));
        vals[2][y][b] = rna_tf32(0.25f * (q00 + q01 - q10 - q11));
        vals[3][y][b] = rna_tf32(0.25f * (q00 - q01 - q10 + q11));
    }
    __syncthreads();
    {
        const int y2 = tid >> 5, b2 = tid & 31;
        const long base = ((long)(xr * 32 + y2) * 128 + ci) * 32 + b2;
        g_A[0 * S_A + base] = vals[0][y2][b2];
        g_A[1 * S_A + base] = vals[1][y2][b2];
        g_A[2 * S_A + base] = vals[2][y2][b2];
        g_A[3 * S_A + base] = vals[3][y2][b2];
    }
}

// ---------------------------------------------------------------------------
// K1b: weight transpose (i,o,u,v) -> [s][uv][k][o], tf32-rna.
// grid (128 k, 4 s), block 256; 8 o-chunks of 16, smem stage 16x260.
// ---------------------------------------------------------------------------
__global__ __launch_bounds__(256) void k_wprep(const float* __restrict__ w0,
                                               const float* __restrict__ w1,
                                               const float* __restrict__ w2,
                                               const float* __restrict__ w3) {
    const int k = blockIdx.x, s = blockIdx.y;
    const float* w = (s == 0) ? w0 : (s == 1) ? w1 : (s == 2) ? w2 : w3;
    __shared__ float t[16][260];
    const int tid = threadIdx.x;

    for (int oc = 0; oc < 8; oc++) {
        // load 16 o x 256 uv (coalesced float4 along uv)
#pragma unroll
        for (int i = tid; i < 1024; i += 256) {
            const int o = i >> 6, uv4 = (i & 63) << 2;
            const float4 v = *reinterpret_cast<const float4*>(
                &w[((long)k * 128 + oc * 16 + o) * 256 + uv4]);
            *reinterpret_cast<float4*>(&t[o][uv4]) = v;
        }
        __syncthreads();
        // write: per uv, 16 contiguous o (4 float4), rna-rounded
#pragma unroll
        for (int pass = 0; pass < 4; pass++) {
            const int uv = pass * 64 + (tid >> 2);
            const int j = tid & 3;
            float4 r;
            r.x = rna_tf32(t[j * 4 + 0][uv]);
            r.y = rna_tf32(t[j * 4 + 1][uv]);
            r.z = rna_tf32(t[j * 4 + 2][uv]);
            r.w = rna_tf32(t[j * 4 + 3][uv]);
            *reinterpret_cast<float4*>(
                &g_Wt[(((long)s * 256 + uv) * 128 + k) * 128 + oc * 16 + j * 4]) = r;
        }
        __syncthreads();
    }
}

// ---------------------------------------------------------------------------
// K2: tap-shared 2x2 tile GEMM, LDG taps + register B-fragments, NO mainloop
// barriers. grid (17 gy, 17 gx, 4 s), block 256 (8 warps), 2 CTAs/SM.
// smem floats: sAp [0,16384) packed A; sR [16384,25600) prologue staging only.
// ---------------------------------------------------------------------------
#define KG_FL   (16384 + 9216 + 32)
#define KG_SMEM (KG_FL * 4)

__device__ __forceinline__ void mma_tf32(float acc[4], const uint32_t a[4],
                                         const uint32_t b[2]) {
    asm volatile(
        "mma.sync.aligned.m16n8k8.row.col.f32.tf32.tf32.f32 "
        "{%0,%1,%2,%3}, {%4,%5,%6,%7}, {%8,%9}, {%0,%1,%2,%3};\n"
        : "+f"(acc[0]), "+f"(acc[1]), "+f"(acc[2]), "+f"(acc[3])
        : "r"(a[0]), "r"(a[1]), "r"(a[2]), "r"(a[3]), "r"(b[0]), "r"(b[1]));
}

__device__ __forceinline__ void cpasync16(uint32_t dst, const void* src) {
    asm volatile("cp.async.cg.shared.global [%0], [%1], 16;"
                 :: "r"(dst), "l"(src));
}

__device__ __forceinline__ void group_meta(int g, int& start, int& np,
                                           int& t0, float c[2][2]) {
    if (g == 0)       { start = 0;  np = 1; t0 = 0;
                        c[0][0] = 1.0f;  c[0][1] = 0.0f; c[1][0] = 0.0f; c[1][1] = 0.0f; }
    else if (g == 16) { start = 31; np = 1; t0 = 15;
                        c[0][0] = 1.0f;  c[0][1] = 0.0f; c[1][0] = 0.0f; c[1][1] = 0.0f; }
    else              { start = 2 * g - 1; np = 2; t0 = g - 1;
                        c[0][0] = 0.75f; c[0][1] = 0.25f;
                        c[1][0] = 0.25f; c[1][1] = 0.75f; }
}

__global__ __launch_bounds__(256, 2) void k_gemm() {
    extern __shared__ float sm[];
    float* sAp = sm;            // 16384 floats
    float* sR  = sm + 16384;    // 9216 floats (prologue staging)

    const int gy = blockIdx.x, gx = blockIdx.y, s = blockIdx.z;
    const int tid = threadIdx.x;

    int xs, npx, u0; float cux[2][2];
    int ys, npy, v0; float cvy[2][2];
    group_meta(gx, xs, npx, u0, cux);
    group_meta(gy, ys, npy, v0, cvy);

    int posi[4];
    const float* Tp[4];
#pragma unroll
    for (int ix = 0; ix < 2; ix++)
#pragma unroll
        for (int iy = 0; iy < 2; iy++)
            posi[ix * 2 + iy] = (xs + (ix < npx ? ix : npx - 1)) * 32
                              + (ys + (iy < npy ? iy : npy - 1));
#pragma unroll
    for (int iu = 0; iu < 2; iu++)
#pragma unroll
        for (int iv = 0; iv < 2; iv++) {
            const int uu = u0 + (iu < npx ? iu : npx - 1);
            const int vv = v0 + (iv < npy ? iv : npy - 1);
            Tp[iu * 2 + iv] = g_Wt + ((long)s * 256 + uu * 16 + vv) * 16384;
        }

    // ---- prologue: stage + repack A in 2 halves (2 positions each) ----
#pragma unroll
    for (int ph = 0; ph < 2; ph++) {
#pragma unroll
        for (int j = 0; j < 8; j++) {
            const int idx = tid + j * 256;        // 0..2047 float4
            const int pl = idx >> 10, li = idx & 1023;
            const int k = li >> 3, b4 = (li & 7) << 2;
            cpasync16((uint32_t)__cvta_generic_to_shared(
                          sR + pl * 4608 + k * 36 + b4),
                      g_A + ((long)s * 1024 + posi[ph * 2 + pl]) * 4096 + li * 4);
        }
        asm volatile("cp.async.commit_group;");
        asm volatile("cp.async.wait_group 0;");
        __syncthreads();
        float4 tmp[8];
#pragma unroll
        for (int i = 0; i < 8; i++) {
            const int fid = i * 256 + tid;        // 0..2047 frags
            const int pl = fid >> 10, r = fid & 1023;
            const int k8 = r >> 6, m = (r >> 5) & 1, lane = r & 31;
            const int gg = lane >> 2, qq = lane & 3;
            const float* rb = sR + pl * 4608;
            tmp[i].x = rb[(8 * k8 + qq) * 36 + 16 * m + gg];
            tmp[i].y = rb[(8 * k8 + qq) * 36 + 16 * m + 8 + gg];
            tmp[i].z = rb[(8 * k8 + qq + 4) * 36 + 16 * m + gg];
            tmp[i].w = rb[(8 * k8 + qq + 4) * 36 + 16 * m + 8 + gg];
        }
#pragma unroll
        for (int i = 0; i < 8; i++) {
            const int fid = i * 256 + tid;
            const int pl = fid >> 10, r = fid & 1023;
            *reinterpret_cast<float4*>(&sAp[((ph * 2 + pl) * 1024 + r) * 4]) = tmp[i];
        }
        __syncthreads();      // repack reads done before next stage overwrites sR
    }
    // sAp now read-only for the rest of the kernel; no further barriers needed.

    const int warp = tid >> 5, lane = tid & 31;
    const int g = lane >> 2, q = lane & 3;
    const int ob = warp << 4;                 // 16 o-cols per warp

    float acc[4][2][2][4];                    // [p][m][n][4]
#pragma unroll
    for (int p = 0; p < 4; p++)
#pragma unroll
        for (int m = 0; m < 2; m++)
#pragma unroll
            for (int n = 0; n < 2; n++)
#pragma unroll
                for (int i = 0; i < 4; i++) acc[p][m][n][i] = 0.0f;

    // per-thread tap base pointers: row q, col ob+g
    const float* tb0 = Tp[0] + q * 128 + ob + g;
    const float* tb1 = Tp[1] + q * 128 + ob + g;
    const float* tb2 = Tp[2] + q * 128 + ob + g;
    const float* tb3 = Tp[3] + q * 128 + ob + g;

    // prefetch kc's 16 tap values: [kk][n][tap]
    auto pref = [&](int kc, float* t) {
#pragma unroll
        for (int kk = 0; kk < 2; kk++)
#pragma unroll
            for (int n = 0; n < 2; n++) {
                const int off = kc * 1024 + kk * 512 + n * 8;
                t[(kk * 2 + n) * 4 + 0] = __ldg(tb0 + off);
                t[(kk * 2 + n) * 4 + 1] = __ldg(tb1 + off);
                t[(kk * 2 + n) * 4 + 2] = __ldg(tb2 + off);
                t[(kk * 2 + n) * 4 + 3] = __ldg(tb3 + off);
            }
    };

    auto compute = [&](const float* t, int kc) {
        float bfv[4][2][2];   // [p][n][kk]
#pragma unroll
        for (int kk = 0; kk < 2; kk++)
#pragma unroll
            for (int n = 0; n < 2; n++) {
                const float t00 = t[(kk * 2 + n) * 4 + 0];
                const float t01 = t[(kk * 2 + n) * 4 + 1];
                const float t10 = t[(kk * 2 + n) * 4 + 2];
                const float t11 = t[(kk * 2 + n) * 4 + 3];
#pragma unroll
                for (int iy = 0; iy < 2; iy++) {
                    const float m0 = cvy[iy][0] * t00 + cvy[iy][1] * t01;
                    const float m1 = cvy[iy][0] * t10 + cvy[iy][1] * t11;
#pragma unroll
                    for (int ix = 0; ix < 2; ix++)
                        bfv[ix * 2 + iy][n][kk] =
                            rna_tf32(cux[ix][0] * m0 + cux[ix][1] * m1);
                }
            }
#pragma unroll
        for (int p = 0; p < 4; p++) {
            uint32_t bf[2][2];
#pragma unroll
            for (int n = 0; n < 2; n++) {
                bf[n][0] = __float_as_uint(bfv[p][n][0]);
                bf[n][1] = __float_as_uint(bfv[p][n][1]);
            }
#pragma unroll
            for (int m = 0; m < 2; m++) {
                const float4 v = *reinterpret_cast<const float4*>(
                    &sAp[(p * 1024 + (kc * 2 + m) * 32 + lane) * 4]);
                uint32_t af[4];
                af[0] = __float_as_uint(v.x);
                af[1] = __float_as_uint(v.y);
                af[2] = __float_as_uint(v.z);
                af[3] = __float_as_uint(v.w);
#pragma unroll
                for (int n = 0; n < 2; n++)
                    mma_tf32(acc[p][m][n], af, bf[n]);
            }
        }
    };

    float tA[16], tB[16];
    pref(0, tA);
#pragma unroll 1
    for (int kc = 0; kc < 16; kc += 2) {
        pref(kc + 1, tB);
        compute(tA, kc);
        if (kc + 2 < 16) pref(kc + 2, tA);
        compute(tB, kc + 1);
    }

    // ---- store C (valid positions only) ----
#pragma unroll
    for (int p = 0; p < 4; p++) {
        const int ix = p >> 1, iy = p & 1;
        if (ix >= npx || iy >= npy) continue;
        float* Cb = g_C + ((long)s * 1024 + posi[p]) * 4096;
#pragma unroll
        for (int m = 0; m < 2; m++)
#pragma unroll
            for (int n = 0; n < 2; n++) {
                const int row = m * 16 + g;
                const int col = ob + n * 8 + q * 2;
                *reinterpret_cast<float2*>(&Cb[row * 128 + col]) =
                    make_float2(acc[p][m][n][0], acc[p][m][n][1]);
                *reinterpret_cast<float2*>(&Cb[(row + 8) * 128 + col]) =
                    make_float2(acc[p][m][n][2], acc[p][m][n][3]);
            }
    }
}

// ---------------------------------------------------------------------------
// K3: idwt + zero-idwt. grid (32 xr, 16 bb, 2 og), block 512 (2 b each).
// dyn smem 2*8448*4 = 67584 B -> 3 CTAs/SM.
// ---------------------------------------------------------------------------
#define K3_SMEM (2 * 8448 * 4)

__global__ __launch_bounds__(512, 3) void k_idwt(float* __restrict__ out) {
    extern __shared__ float sC[];   // [hb][(s*32+y)][o_loc] stride 66
    const int xr = blockIdx.x, bb = blockIdx.y, og = blockIdx.z;
    const int tid = threadIdx.x;
    const int hb = tid >> 8, lt = tid & 255;
    const int b = bb * 2 + hb;
    float* sB = sC + hb * 8448;

    const float4* Cg = reinterpret_cast<const float4*>(g_C);
#pragma unroll
    for (int i = 0; i < 8; i++) {
        const int fid = i * 256 + lt;
        const int row = fid >> 4, c4 = fid & 15;
        const int ss = row >> 5, y = row & 31;
        const float4 v = Cg[(((long)ss * 1024 + xr * 32 + y) * 32 + b) * 32
                            + og * 16 + c4];
        float* d = &sB[row * 66 + c4 * 4];
        d[0] = v.x; d[1] = v.y; d[2] = v.z; d[3] = v.w;
    }
    __syncthreads();

    const int y = lt & 31;
    const int t8 = lt >> 5;
    const long ob0 = ((long)b * 128 + og * 64) * 16384 + (4 * xr) * 128 + 4 * y;

#pragma unroll
    for (int j = 0; j < 8; j++) {
        const int ol = t8 * 8 + j;
        const float ll = sB[(0 * 32 + y) * 66 + ol];
        const float lh = sB[(1 * 32 + y) * 66 + ol];
        const float hl = sB[(2 * 32 + y) * 66 + ol];
        const float hh = sB[(3 * 32 + y) * 66 + ol];
        const float e00 = 0.25f * (ll + lh + hl + hh);
        const float e01 = 0.25f * (ll - lh + hl - hh);
        const float e10 = 0.25f * (ll + lh - hl - hh);
        const float e11 = 0.25f * (ll - lh - hl + hh);
        float* p = out + ob0 + (long)ol * 16384;
        const float4 top = make_float4(e00, e00, e01, e01);
        const float4 bot = make_float4(e10, e10, e11, e11);
        *reinterpret_cast<float4*>(p)       = top;
        *reinterpret_cast<float4*>(p + 128) = top;
        *reinterpret_cast<float4*>(p + 256) = bot;
        *reinterpret_cast<float4*>(p + 384) = bot;
    }
}

// ---------------------------------------------------------------------------
extern "C" void kernel_launch(void* const* d_in, const int* in_sizes, int n_in,
                              void* d_out, int out_size) {
    (void)in_sizes; (void)n_in; (void)out_size;
    const float* x  = (const float*)d_in[0];
    const float* w1 = (const float*)d_in[1];
    const float* w2 = (const float*)d_in[2];
    const float* w3 = (const float*)d_in[3];
    const float* w4 = (const float*)d_in[4];

    cudaFuncSetAttribute(k_gemm, cudaFuncAttributeMaxDynamicSharedMemorySize, KG_SMEM);
    cudaFuncSetAttribute(k_idwt, cudaFuncAttributeMaxDynamicSharedMemorySize, K3_SMEM);

    k_dwt  <<<dim3(32, 128), 1024>>>(x);
    k_wprep<<<dim3(128, 4), 256>>>(w1, w2, w3, w4);
    k_gemm <<<dim3(17, 17, 4), 256, KG_SMEM>>>();
    k_idwt <<<dim3(32, 16, 2), 512, K3_SMEM>>>((float*)d_out);
}

// round 14
// speedup vs baseline: 3.3951x; 1.1305x over previous
#include <cuda_runtime.h>
#include <cuda_fp16.h>
#include <cstdint>

// ---------------------------------------------------------------------------
// FlexibleWaveConv2d, round 14 — fp16 tensor path (tf32-equal precision).
//   K1 k_dwt  : x -> A2[s][pos][k2][b] half2 (channel pairs packed)
//   K2 k_wprep: w_s -> W2[s][uv][k2][o] half2 (k-pairs, scaled by 2^12)
//   K3 k_gemm : 2x2 tap-shared position tiles, barrier-free mainloop,
//               taps via LDG (register double buffer), B-fragments
//               interpolated in registers, mma.sync m16n8k16 f16 -> g_C
//               (scaled back by 2^-12 at store).
//   K4 k_idwt : C -> out (unchanged from R12).
// ---------------------------------------------------------------------------

#define N_A2 (4L*1024*64*32)
#define N_W2 (4L*256*64*128)
#define N_C  (4L*1024*32*128)

static __device__ __half2 g_A2[N_A2];  // [s][pos][k2][b]
static __device__ __half2 g_W2[N_W2];  // [s][u*16+v][k2][o], x 4096
static __device__ float   g_C [N_C];   // [s][pos][b][o]

// ---------------------------------------------------------------------------
// K1: 4x4 block Haar, 2 channels per block, half2-packed output.
// grid (32 xr, 64 cp), block 1024.
// ---------------------------------------------------------------------------
__global__ __launch_bounds__(1024) void k_dwt(const float* __restrict__ x) {
    const int xr = blockIdx.x, cp = blockIdx.y;
    __shared__ float vals[2][4][32][33];
    const int tid = threadIdx.x;
    const int b = tid >> 5, y = tid & 31;

#pragma unroll
    for (int ph = 0; ph < 2; ph++) {
        const int ci = 2 * cp + ph;
        const float4* px = reinterpret_cast<const float4*>(x)
                         + ((long)(b * 128 + ci) * 128 + 4 * xr) * 32 + y;
        float4 r0 = px[0], r1 = px[32], r2 = px[64], r3 = px[96];
        float q00 = r0.x + r0.y + r1.x + r1.y;
        float q01 = r0.z + r0.w + r1.z + r1.w;
        float q10 = r2.x + r2.y + r3.x + r3.y;
        float q11 = r2.z + r2.w + r3.z + r3.w;
        vals[ph][0][y][b] = 0.25f * (q00 + q01 + q10 + q11);
        vals[ph][1][y][b] = 0.25f * (q00 - q01 + q10 - q11);
        vals[ph][2][y][b] = 0.25f * (q00 + q01 - q10 - q11);
        vals[ph][3][y][b] = 0.25f * (q00 - q01 - q10 + q11);
    }
    __syncthreads();
    const int y2 = tid >> 5, b2 = tid & 31;
#pragma unroll
    for (int s = 0; s < 4; s++) {
        g_A2[(((long)s * 1024 + xr * 32 + y2) * 64 + cp) * 32 + b2] =
            __floats2half2_rn(vals[0][s][y2][b2], vals[1][s][y2][b2]);
    }
}

// ---------------------------------------------------------------------------
// K2: weight transpose (i,o,u,v) -> [s][uv][k2][o] half2, scaled by 4096.
// grid (64 k2, 4 s), block 256.
// ---------------------------------------------------------------------------
__global__ __launch_bounds__(256) void k_wprep(const float* __restrict__ w0,
                                               const float* __restrict__ w1,
                                               const float* __restrict__ w2,
                                               const float* __restrict__ w3) {
    const int k2 = blockIdx.x, s = blockIdx.y;
    const float* w = (s == 0) ? w0 : (s == 1) ? w1 : (s == 2) ? w2 : w3;
    __shared__ float t[2][16][260];
    const int tid = threadIdx.x;

    for (int oc = 0; oc < 8; oc++) {
        for (int idx = tid; idx < 2048; idx += 256) {
            const int kk = idx >> 10, r = idx & 1023;
            const int o = r >> 6, uv4 = (r & 63) << 2;
            const float4 v = *reinterpret_cast<const float4*>(
                &w[((long)(2 * k2 + kk) * 128 + oc * 16 + o) * 256 + uv4]);
            *reinterpret_cast<float4*>(&t[kk][o][uv4]) = v;
        }
        __syncthreads();
        const int oj = tid & 15, uvg = tid >> 4;
#pragma unroll
        for (int uvp = 0; uvp < 16; uvp++) {
            const int uv = uvp * 16 + uvg;
            g_W2[(((long)s * 256 + uv) * 64 + k2) * 128 + oc * 16 + oj] =
                __floats2half2_rn(4096.0f * t[0][oj][uv],
                                  4096.0f * t[1][oj][uv]);
        }
        __syncthreads();
    }
}

// ---------------------------------------------------------------------------
// K3: fp16 tap-shared 2x2 tile GEMM. grid (17 gy, 17 gx, 4 s), block 256,
// 2 CTAs/SM. smem: sAp 32 KB (fragment-packed A, direct-LDG prologue).
// ---------------------------------------------------------------------------
__device__ __forceinline__ void mma_f16(float acc[4], const uint32_t a[4],
                                        const uint32_t b[2]) {
    asm volatile(
        "mma.sync.aligned.m16n8k16.row.col.f32.f16.f16.f32 "
        "{%0,%1,%2,%3}, {%4,%5,%6,%7}, {%8,%9}, {%0,%1,%2,%3};\n"
        : "+f"(acc[0]), "+f"(acc[1]), "+f"(acc[2]), "+f"(acc[3])
        : "r"(a[0]), "r"(a[1]), "r"(a[2]), "r"(a[3]), "r"(b[0]), "r"(b[1]));
}

__device__ __forceinline__ void group_meta(int g, int& start, int& np,
                                           int& t0, float c[2][2]) {
    if (g == 0)       { start = 0;  np = 1; t0 = 0;
                        c[0][0] = 1.0f;  c[0][1] = 0.0f; c[1][0] = 0.0f; c[1][1] = 0.0f; }
    else if (g == 16) { start = 31; np = 1; t0 = 15;
                        c[0][0] = 1.0f;  c[0][1] = 0.0f; c[1][0] = 0.0f; c[1][1] = 0.0f; }
    else              { start = 2 * g - 1; np = 2; t0 = g - 1;
                        c[0][0] = 0.75f; c[0][1] = 0.25f;
                        c[1][0] = 0.25f; c[1][1] = 0.75f; }
}

__global__ __launch_bounds__(256, 2) void k_gemm() {
    __shared__ uint4 sAp[2048];   // frag id = p*512 + kc*64 + m*32 + lane

    const int gy = blockIdx.x, gx = blockIdx.y, s = blockIdx.z;
    const int tid = threadIdx.x;

    int xs, npx, u0; float cux[2][2];
    int ys, npy, v0; float cvy[2][2];
    group_meta(gx, xs, npx, u0, cux);
    group_meta(gy, ys, npy, v0, cvy);

    int posi[4], uvoff[4];
#pragma unroll
    for (int ix = 0; ix < 2; ix++)
#pragma unroll
        for (int iy = 0; iy < 2; iy++)
            posi[ix * 2 + iy] = (xs + (ix < npx ? ix : npx - 1)) * 32
                              + (ys + (iy < npy ? iy : npy - 1));
#pragma unroll
    for (int iu = 0; iu < 2; iu++)
#pragma unroll
        for (int iv = 0; iv < 2; iv++) {
            const int uu = u0 + (iu < npx ? iu : npx - 1);
            const int vv = v0 + (iv < npy ? iv : npy - 1);
            uvoff[iu * 2 + iv] = uu * 16 + vv;
        }

    // ---- prologue: direct-LDG A fragments into sAp ----
#pragma unroll
    for (int j = 0; j < 8; j++) {
        const int id = j * 256 + tid;
        const int p = id >> 9, rem = id & 511;
        const int kc = rem >> 6, m2 = (rem >> 5) & 1, ln = rem & 31;
        const int gg = ln >> 2, qq = ln & 3;
        const uint32_t* Ab = reinterpret_cast<const uint32_t*>(
            g_A2 + ((long)s * 1024 + posi[p]) * 2048);
        const int r0 = (kc * 8 + qq) * 32 + m2 * 16 + gg;
        const int r1 = (kc * 8 + qq + 4) * 32 + m2 * 16 + gg;
        uint4 v;
        v.x = __ldg(Ab + r0);
        v.y = __ldg(Ab + r0 + 8);
        v.z = __ldg(Ab + r1);
        v.w = __ldg(Ab + r1 + 8);
        sAp[id] = v;
    }
    __syncthreads();

    const int warp = tid >> 5, lane = tid & 31;
    const int g = lane >> 2, q = lane & 3;
    const int ob = warp << 4;                 // 16 o-cols per warp

    float acc[4][2][2][4];
#pragma unroll
    for (int p = 0; p < 4; p++)
#pragma unroll
        for (int m = 0; m < 2; m++)
#pragma unroll
            for (int n = 0; n < 2; n++)
#pragma unroll
                for (int i = 0; i < 4; i++) acc[p][m][n][i] = 0.0f;

    // per-thread tap pointers: element (k2 = q (+4*reg) + kc*8, o = ob+g (+n*8))
    const uint32_t* tb[4];
#pragma unroll
    for (int j = 0; j < 4; j++)
        tb[j] = reinterpret_cast<const uint32_t*>(
                    g_W2 + ((long)s * 256 + uvoff[j]) * 8192)
                + q * 128 + ob + g;

    auto pref = [&](int kc, uint32_t* t) {
#pragma unroll
        for (int n = 0; n < 2; n++)
#pragma unroll
            for (int reg = 0; reg < 2; reg++) {
                const int off = kc * 1024 + reg * 512 + n * 8;
                const int base = (n * 2 + reg) * 4;
                t[base + 0] = __ldg(tb[0] + off);
                t[base + 1] = __ldg(tb[1] + off);
                t[base + 2] = __ldg(tb[2] + off);
                t[base + 3] = __ldg(tb[3] + off);
            }
    };

    auto compute = [&](const uint32_t* t, int kc) {
        uint32_t bf[4][2][2];   // [p][n][reg]
#pragma unroll
        for (int n = 0; n < 2; n++)
#pragma unroll
            for (int reg = 0; reg < 2; reg++) {
                const int base = (n * 2 + reg) * 4;
                const float2 t00 = __half22float2(
                    *reinterpret_cast<const __half2*>(&t[base + 0]));
                const float2 t01 = __half22float2(
                    *reinterpret_cast<const __half2*>(&t[base + 1]));
                const float2 t10 = __half22float2(
                    *reinterpret_cast<const __half2*>(&t[base + 2]));
                const float2 t11 = __half22float2(
                    *reinterpret_cast<const __half2*>(&t[base + 3]));
#pragma unroll
                for (int iy = 0; iy < 2; iy++) {
                    float2 m0, m1;
                    m0.x = cvy[iy][0] * t00.x + cvy[iy][1] * t01.x;
                    m0.y = cvy[iy][0] * t00.y + cvy[iy][1] * t01.y;
                    m1.x = cvy[iy][0] * t10.x + cvy[iy][1] * t11.x;
                    m1.y = cvy[iy][0] * t10.y + cvy[iy][1] * t11.y;
#pragma unroll
                    for (int ix = 0; ix < 2; ix++) {
                        const float vx = cux[ix][0] * m0.x + cux[ix][1] * m1.x;
                        const float vy = cux[ix][0] * m0.y + cux[ix][1] * m1.y;
                        const __half2 h = __floats2half2_rn(vx, vy);
                        bf[ix * 2 + iy][n][reg] =
                            *reinterpret_cast<const uint32_t*>(&h);
                    }
                }
            }
#pragma unroll
        for (int p = 0; p < 4; p++) {
            const uint4 a0 = sAp[p * 512 + kc * 64 + lane];
            const uint4 a1 = sAp[p * 512 + kc * 64 + 32 + lane];
            const uint32_t af0[4] = {a0.x, a0.y, a0.z, a0.w};
            const uint32_t af1[4] = {a1.x, a1.y, a1.z, a1.w};
#pragma unroll
            for (int n = 0; n < 2; n++) {
                const uint32_t bb[2] = {bf[p][n][0], bf[p][n][1]};
                mma_f16(acc[p][0][n], af0, bb);
                mma_f16(acc[p][1][n], af1, bb);
            }
        }
    };

    uint32_t tA[16], tB[16];
    pref(0, tA);
#pragma unroll 1
    for (int kc = 0; kc < 8; kc += 2) {
        pref(kc + 1, tB);
        compute(tA, kc);
        if (kc + 2 < 8) pref(kc + 2, tA);
        compute(tB, kc + 1);
    }

    // ---- store C (unscale by 2^-12; valid positions only) ----
    const float INV = 1.0f / 4096.0f;
#pragma unroll
    for (int p = 0; p < 4; p++) {
        const int ix = p >> 1, iy = p & 1;
        if (ix >= npx || iy >= npy) continue;
        float* Cb = g_C + ((long)s * 1024 + posi[p]) * 4096;
#pragma unroll
        for (int m = 0; m < 2; m++)
#pragma unroll
            for (int n = 0; n < 2; n++) {
                const int row = m * 16 + g;
                const int col = ob + n * 8 + q * 2;
                *reinterpret_cast<float2*>(&Cb[row * 128 + col]) =
                    make_float2(acc[p][m][n][0] * INV, acc[p][m][n][1] * INV);
                *reinterpret_cast<float2*>(&Cb[(row + 8) * 128 + col]) =
                    make_float2(acc[p][m][n][2] * INV, acc[p][m][n][3] * INV);
            }
    }
}

// ---------------------------------------------------------------------------
// K4: idwt + zero-idwt. grid (32 xr, 16 bb, 2 og), block 512 (2 b each).
// dyn smem 2*8448*4 = 67584 B -> 3 CTAs/SM.
// ---------------------------------------------------------------------------
#define K3_SMEM (2 * 8448 * 4)

__global__ __launch_bounds__(512, 3) void k_idwt(float* __restrict__ out) {
    extern __shared__ float sC[];   // [hb][(s*32+y)][o_loc] stride 66
    const int xr = blockIdx.x, bb = blockIdx.y, og = blockIdx.z;
    const int tid = threadIdx.x;
    const int hb = tid >> 8, lt = tid & 255;
    const int b = bb * 2 + hb;
    float* sB = sC + hb * 8448;

    const float4* Cg = reinterpret_cast<const float4*>(g_C);
#pragma unroll
    for (int i = 0; i < 8; i++) {
        const int fid = i * 256 + lt;
        const int row = fid >> 4, c4 = fid & 15;
        const int ss = row >> 5, y = row & 31;
        const float4 v = Cg[(((long)ss * 1024 + xr * 32 + y) * 32 + b) * 32
                            + og * 16 + c4];
        float* d = &sB[row * 66 + c4 * 4];
        d[0] = v.x; d[1] = v.y; d[2] = v.z; d[3] = v.w;
    }
    __syncthreads();

    const int y = lt & 31;
    const int t8 = lt >> 5;
    const long ob0 = ((long)b * 128 + og * 64) * 16384 + (4 * xr) * 128 + 4 * y;

#pragma unroll
    for (int j = 0; j < 8; j++) {
        const int ol = t8 * 8 + j;
        const float ll = sB[(0 * 32 + y) * 66 + ol];
        const float lh = sB[(1 * 32 + y) * 66 + ol];
        const float hl = sB[(2 * 32 + y) * 66 + ol];
        const float hh = sB[(3 * 32 + y) * 66 + ol];
        const float e00 = 0.25f * (ll + lh + hl + hh);
        const float e01 = 0.25f * (ll - lh + hl - hh);
        const float e10 = 0.25f * (ll + lh - hl - hh);
        const float e11 = 0.25f * (ll - lh - hl + hh);
        float* p = out + ob0 + (long)ol * 16384;
        const float4 top = make_float4(e00, e00, e01, e01);
        const float4 bot = make_float4(e10, e10, e11, e11);
        *reinterpret_cast<float4*>(p)       = top;
        *reinterpret_cast<float4*>(p + 128) = top;
        *reinterpret_cast<float4*>(p + 256) = bot;
        *reinterpret_cast<float4*>(p + 384) = bot;
    }
}

// ---------------------------------------------------------------------------
extern "C" void kernel_launch(void* const* d_in, const int* in_sizes, int n_in,
                              void* d_out, int out_size) {
    (void)in_sizes; (void)n_in; (void)out_size;
    const float* x  = (const float*)d_in[0];
    const float* w1 = (const float*)d_in[1];
    const float* w2 = (const float*)d_in[2];
    const float* w3 = (const float*)d_in[3];
    const float* w4 = (const float*)d_in[4];

    cudaFuncSetAttribute(k_idwt, cudaFuncAttributeMaxDynamicSharedMemorySize,
                         K3_SMEM);

    k_dwt  <<<dim3(32, 64), 1024>>>(x);
    k_wprep<<<dim3(64, 4), 256>>>(w1, w2, w3, w4);
    k_gemm <<<dim3(17, 17, 4), 256>>>();
    k_idwt <<<dim3(32, 16, 2), 512, K3_SMEM>>>((float*)d_out);
}

// round 16
// speedup vs baseline: 3.5976x; 1.0596x over previous
#include <cuda_runtime.h>
#include <cuda_fp16.h>
#include <cstdint>

// ---------------------------------------------------------------------------
// FlexibleWaveConv2d, round 15 — fp16 path with HFMA2 interp + half2 C.
//   K1 k_dwt  : x -> A2[s][pos][k2][b] half2 (channel pairs packed)
//   K2 k_wprep: w_s -> W2[s][uv][k2][o] half2 (k-pairs, scaled by 2^12)
//   K3 k_gemm : 2x2 tap-shared position tiles, barrier-free mainloop,
//               taps via LDG (register double buffer), B-fragments
//               interpolated with HFMA2 (native half2), mma m16n8k16 f16,
//               C stored as half2 (still scaled by 2^12).
//   K4 k_idwt : C(half2) -> out fp32 (unscale by 2^-12 folded into 0.25).
// ---------------------------------------------------------------------------

#define N_A2 (4L*1024*64*32)
#define N_W2 (4L*256*64*128)
#define N_C2 (4L*1024*32*64)

static __device__ __half2 g_A2[N_A2];  // [s][pos][k2][b]
static __device__ __half2 g_W2[N_W2];  // [s][u*16+v][k2][o], x 4096
static __device__ __half2 g_C2[N_C2];  // [s][pos][b][o2], x 4096

// ---------------------------------------------------------------------------
// K1: 4x4 block Haar, 2 channels per block, half2-packed output.
// grid (32 xr, 64 cp), block 1024.
// ---------------------------------------------------------------------------
__global__ __launch_bounds__(1024) void k_dwt(const float* __restrict__ x) {
    const int xr = blockIdx.x, cp = blockIdx.y;
    __shared__ float vals[2][4][32][33];
    const int tid = threadIdx.x;
    const int b = tid >> 5, y = tid & 31;

#pragma unroll
    for (int ph = 0; ph < 2; ph++) {
        const int ci = 2 * cp + ph;
        const float4* px = reinterpret_cast<const float4*>(x)
                         + ((long)(b * 128 + ci) * 128 + 4 * xr) * 32 + y;
        float4 r0 = px[0], r1 = px[32], r2 = px[64], r3 = px[96];
        float q00 = r0.x + r0.y + r1.x + r1.y;
        float q01 = r0.z + r0.w + r1.z + r1.w;
        float q10 = r2.x + r2.y + r3.x + r3.y;
        float q11 = r2.z + r2.w + r3.z + r3.w;
        vals[ph][0][y][b] = 0.25f * (q00 + q01 + q10 + q11);
        vals[ph][1][y][b] = 0.25f * (q00 - q01 + q10 - q11);
        vals[ph][2][y][b] = 0.25f * (q00 + q01 - q10 - q11);
        vals[ph][3][y][b] = 0.25f * (q00 - q01 - q10 + q11);
    }
    __syncthreads();
    const int y2 = tid >> 5, b2 = tid & 31;
#pragma unroll
    for (int s = 0; s < 4; s++) {
        g_A2[(((long)s * 1024 + xr * 32 + y2) * 64 + cp) * 32 + b2] =
            __floats2half2_rn(vals[0][s][y2][b2], vals[1][s][y2][b2]);
    }
}

// ---------------------------------------------------------------------------
// K2: weight transpose (i,o,u,v) -> [s][uv][k2][o] half2, scaled by 4096.
// grid (64 k2, 4 s), block 256.
// ---------------------------------------------------------------------------
__global__ __launch_bounds__(256) void k_wprep(const float* __restrict__ w0,
                                               const float* __restrict__ w1,
                                               const float* __restrict__ w2,
                                               const float* __restrict__ w3) {
    const int k2 = blockIdx.x, s = blockIdx.y;
    const float* w = (s == 0) ? w0 : (s == 1) ? w1 : (s == 2) ? w2 : w3;
    __shared__ float t[2][16][260];
    const int tid = threadIdx.x;

    for (int oc = 0; oc < 8; oc++) {
        for (int idx = tid; idx < 2048; idx += 256) {
            const int kk = idx >> 10, r = idx & 1023;
            const int o = r >> 6, uv4 = (r & 63) << 2;
            const float4 v = *reinterpret_cast<const float4*>(
                &w[((long)(2 * k2 + kk) * 128 + oc * 16 + o) * 256 + uv4]);
            *reinterpret_cast<float4*>(&t[kk][o][uv4]) = v;
        }
        __syncthreads();
        const int oj = tid & 15, uvg = tid >> 4;
#pragma unroll
        for (int uvp = 0; uvp < 16; uvp++) {
            const int uv = uvp * 16 + uvg;
            g_W2[(((long)s * 256 + uv) * 64 + k2) * 128 + oc * 16 + oj] =
                __floats2half2_rn(4096.0f * t[0][oj][uv],
                                  4096.0f * t[1][oj][uv]);
        }
        __syncthreads();
    }
}

// ---------------------------------------------------------------------------
// K3: fp16 tap-shared 2x2 tile GEMM, HFMA2 interp.
// grid (17 gy, 17 gx, 4 s), block 256, 2 CTAs/SM. smem 32 KB.
// ---------------------------------------------------------------------------
__device__ __forceinline__ void mma_f16(float acc[4], const uint32_t a[4],
                                        const uint32_t b[2]) {
    asm volatile(
        "mma.sync.aligned.m16n8k16.row.col.f32.f16.f16.f32 "
        "{%0,%1,%2,%3}, {%4,%5,%6,%7}, {%8,%9}, {%0,%1,%2,%3};\n"
        : "+f"(acc[0]), "+f"(acc[1]), "+f"(acc[2]), "+f"(acc[3])
        : "r"(a[0]), "r"(a[1]), "r"(a[2]), "r"(a[3]), "r"(b[0]), "r"(b[1]));
}

__device__ __forceinline__ void group_meta(int g, int& start, int& np,
                                           int& t0, float c[2][2]) {
    if (g == 0)       { start = 0;  np = 1; t0 = 0;
                        c[0][0] = 1.0f;  c[0][1] = 0.0f; c[1][0] = 0.0f; c[1][1] = 0.0f; }
    else if (g == 16) { start = 31; np = 1; t0 = 15;
                        c[0][0] = 1.0f;  c[0][1] = 0.0f; c[1][0] = 0.0f; c[1][1] = 0.0f; }
    else              { start = 2 * g - 1; np = 2; t0 = g - 1;
                        c[0][0] = 0.75f; c[0][1] = 0.25f;
                        c[1][0] = 0.25f; c[1][1] = 0.75f; }
}

__global__ __launch_bounds__(256, 2) void k_gemm() {
    __shared__ uint4 sAp[2048];   // frag id = p*512 + kc*64 + m*32 + lane

    const int gy = blockIdx.x, gx = blockIdx.y, s = blockIdx.z;
    const int tid = threadIdx.x;

    int xs, npx, u0; float cux[2][2];
    int ys, npy, v0; float cvy[2][2];
    group_meta(gx, xs, npx, u0, cux);
    group_meta(gy, ys, npy, v0, cvy);

    // fp16 broadcast coefficients (0.25/0.75/1.0/0.0 exact)
    __half2 cuh[2][2], cvh[2][2];
#pragma unroll
    for (int i = 0; i < 2; i++)
#pragma unroll
        for (int j = 0; j < 2; j++) {
            cuh[i][j] = __half2half2(__float2half_rn(cux[i][j]));
            cvh[i][j] = __half2half2(__float2half_rn(cvy[i][j]));
        }

    int posi[4], uvoff[4];
#pragma unroll
    for (int ix = 0; ix < 2; ix++)
#pragma unroll
        for (int iy = 0; iy < 2; iy++)
            posi[ix * 2 + iy] = (xs + (ix < npx ? ix : npx - 1)) * 32
                              + (ys + (iy < npy ? iy : npy - 1));
#pragma unroll
    for (int iu = 0; iu < 2; iu++)
#pragma unroll
        for (int iv = 0; iv < 2; iv++) {
            const int uu = u0 + (iu < npx ? iu : npx - 1);
            const int vv = v0 + (iv < npy ? iv : npy - 1);
            uvoff[iu * 2 + iv] = uu * 16 + vv;
        }

    // ---- prologue: direct-LDG A fragments into sAp ----
#pragma unroll
    for (int j = 0; j < 8; j++) {
        const int id = j * 256 + tid;
        const int p = id >> 9, rem = id & 511;
        const int kc = rem >> 6, m2 = (rem >> 5) & 1, ln = rem & 31;
        const int gg = ln >> 2, qq = ln & 3;
        const uint32_t* Ab = reinterpret_cast<const uint32_t*>(
            g_A2 + ((long)s * 1024 + posi[p]) * 2048);
        const int r0 = (kc * 8 + qq) * 32 + m2 * 16 + gg;
        const int r1 = (kc * 8 + qq + 4) * 32 + m2 * 16 + gg;
        uint4 v;
        v.x = __ldg(Ab + r0);
        v.y = __ldg(Ab + r0 + 8);
        v.z = __ldg(Ab + r1);
        v.w = __ldg(Ab + r1 + 8);
        sAp[id] = v;
    }
    __syncthreads();

    const int warp = tid >> 5, lane = tid & 31;
    const int g = lane >> 2, q = lane & 3;
    const int ob = warp << 4;                 // 16 o-cols per warp

    float acc[4][2][2][4];
#pragma unroll
    for (int p = 0; p < 4; p++)
#pragma unroll
        for (int m = 0; m < 2; m++)
#pragma unroll
            for (int n = 0; n < 2; n++)
#pragma unroll
                for (int i = 0; i < 4; i++) acc[p][m][n][i] = 0.0f;

    const uint32_t* tb[4];
#pragma unroll
    for (int j = 0; j < 4; j++)
        tb[j] = reinterpret_cast<const uint32_t*>(
                    g_W2 + ((long)s * 256 + uvoff[j]) * 8192)
                + q * 128 + ob + g;

    auto pref = [&](int kc, uint32_t* t) {
#pragma unroll
        for (int n = 0; n < 2; n++)
#pragma unroll
            for (int reg = 0; reg < 2; reg++) {
                const int off = kc * 1024 + reg * 512 + n * 8;
                const int base = (n * 2 + reg) * 4;
                t[base + 0] = __ldg(tb[0] + off);
                t[base + 1] = __ldg(tb[1] + off);
                t[base + 2] = __ldg(tb[2] + off);
                t[base + 3] = __ldg(tb[3] + off);
            }
    };

    auto compute = [&](const uint32_t* t, int kc) {
        uint32_t bf[4][2][2];   // [p][n][reg]
#pragma unroll
        for (int n = 0; n < 2; n++)
#pragma unroll
            for (int reg = 0; reg < 2; reg++) {
                const int base = (n * 2 + reg) * 4;
                const __half2 t00 = *reinterpret_cast<const __half2*>(&t[base + 0]);
                const __half2 t01 = *reinterpret_cast<const __half2*>(&t[base + 1]);
                const __half2 t10 = *reinterpret_cast<const __half2*>(&t[base + 2]);
                const __half2 t11 = *reinterpret_cast<const __half2*>(&t[base + 3]);
#pragma unroll
                for (int iy = 0; iy < 2; iy++) {
                    const __half2 m0 = __hfma2(cvh[iy][0], t00,
                                               __hmul2(cvh[iy][1], t01));
                    const __half2 m1 = __hfma2(cvh[iy][0], t10,
                                               __hmul2(cvh[iy][1], t11));
#pragma unroll
                    for (int ix = 0; ix < 2; ix++) {
                        const __half2 r = __hfma2(cuh[ix][0], m0,
                                                  __hmul2(cuh[ix][1], m1));
                        bf[ix * 2 + iy][n][reg] =
                            *reinterpret_cast<const uint32_t*>(&r);
                    }
                }
            }
#pragma unroll
        for (int p = 0; p < 4; p++) {
            const uint4 a0 = sAp[p * 512 + kc * 64 + lane];
            const uint4 a1 = sAp[p * 512 + kc * 64 + 32 + lane];
            const uint32_t af0[4] = {a0.x, a0.y, a0.z, a0.w};
            const uint32_t af1[4] = {a1.x, a1.y, a1.z, a1.w};
#pragma unroll
            for (int n = 0; n < 2; n++) {
                const uint32_t bb[2] = {bf[p][n][0], bf[p][n][1]};
                mma_f16(acc[p][0][n], af0, bb);
                mma_f16(acc[p][1][n], af1, bb);
            }
        }
    };

    uint32_t tA[16], tB[16];
    pref(0, tA);
#pragma unroll 1
    for (int kc = 0; kc < 8; kc += 2) {
        pref(kc + 1, tB);
        compute(tA, kc);
        if (kc + 2 < 8) pref(kc + 2, tA);
        compute(tB, kc + 1);
    }

    // ---- store C as half2 (still scaled by 4096; valid positions only) ----
#pragma unroll
    for (int p = 0; p < 4; p++) {
        const int ix = p >> 1, iy = p & 1;
        if (ix >= npx || iy >= npy) continue;
        __half2* Cb = g_C2 + ((long)s * 1024 + posi[p]) * 2048;
#pragma unroll
        for (int m = 0; m < 2; m++)
#pragma unroll
            for (int n = 0; n < 2; n++) {
                const int row = m * 16 + g;
                const int col2 = (ob >> 1) + n * 4 + q;
                Cb[row * 64 + col2] =
                    __floats2half2_rn(acc[p][m][n][0], acc[p][m][n][1]);
                Cb[(row + 8) * 64 + col2] =
                    __floats2half2_rn(acc[p][m][n][2], acc[p][m][n][3]);
            }
    }
}

// ---------------------------------------------------------------------------
// K4: idwt + zero-idwt from half2 C. grid (32 xr, 16 bb, 2 og), block 512.
// smem 2 x 128 x 33 uint32 = 33792 B (static). Unscale folded into 0.25/4096.
// ---------------------------------------------------------------------------
__global__ __launch_bounds__(512, 3) void k_idwt(float* __restrict__ out) {
    __shared__ uint32_t sU[2 * 128 * 33];
    const int xr = blockIdx.x, bb = blockIdx.y, og = blockIdx.z;
    const int tid = threadIdx.x;
    const int hb = tid >> 8, lt = tid & 255;
    const int b = bb * 2 + hb;
    uint32_t* sB = sU + hb * 4224;

    const uint4* Cg = reinterpret_cast<const uint4*>(g_C2);
#pragma unroll
    for (int i = 0; i < 4; i++) {
        const int fid = i * 256 + lt;
        const int row = fid >> 3, c4 = fid & 7;    // row = s*32+y, 8 uint4/row
        const int ss = row >> 5, y = row & 31;
        const uint4 v = Cg[((((long)ss * 1024 + xr * 32 + y) * 32 + b) * 16)
                           + og * 8 + c4];
        uint32_t* d = &sB[row * 33 + c4 * 4];
        d[0] = v.x; d[1] = v.y; d[2] = v.z; d[3] = v.w;
    }
    __syncthreads();

    const int y = lt & 31;
    const int t8 = lt >> 5;
    const float SC = 0.25f / 4096.0f;
    const long ob0 = ((long)b * 128 + og * 64) * 16384 + (4 * xr) * 128 + 4 * y;

#pragma unroll
    for (int j = 0; j < 4; j++) {
        const int o2l = t8 * 4 + j;                // local half2 idx (0..31)
        const float2 ll = __half22float2(*reinterpret_cast<const __half2*>(
            &sB[(0 * 32 + y) * 33 + o2l]));
        const float2 lh = __half22float2(*reinterpret_cast<const __half2*>(
            &sB[(1 * 32 + y) * 33 + o2l]));
        const float2 hl = __half22float2(*reinterpret_cast<const __half2*>(
            &sB[(2 * 32 + y) * 33 + o2l]));
        const float2 hh = __half22float2(*reinterpret_cast<const __half2*>(
            &sB[(3 * 32 + y) * 33 + o2l]));
#pragma unroll
        for (int comp = 0; comp < 2; comp++) {
            const float l0 = comp ? ll.y : ll.x;
            const float l1 = comp ? lh.y : lh.x;
            const float h0 = comp ? hl.y : hl.x;
            const float h1 = comp ? hh.y : hh.x;
            const float e00 = SC * (l0 + l1 + h0 + h1);
            const float e01 = SC * (l0 - l1 + h0 - h1);
            const float e10 = SC * (l0 + l1 - h0 - h1);
            const float e11 = SC * (l0 - l1 - h0 + h1);
            float* p = out + ob0 + (long)(2 * o2l + comp) * 16384;
            const float4 top = make_float4(e00, e00, e01, e01);
            const float4 bot = make_float4(e10, e10, e11, e11);
            *reinterpret_cast<float4*>(p)       = top;
            *reinterpret_cast<float4*>(p + 128) = top;
            *reinterpret_cast<float4*>(p + 256) = bot;
            *reinterpret_cast<float4*>(p + 384) = bot;
        }
    }
}

// ---------------------------------------------------------------------------
extern "C" void kernel_launch(void* const* d_in, const int* in_sizes, int n_in,
                              void* d_out, int out_size) {
    (void)in_sizes; (void)n_in; (void)out_size;
    const float* x  = (const float*)d_in[0];
    const float* w1 = (const float*)d_in[1];
    const float* w2 = (const float*)d_in[2];
    const float* w3 = (const float*)d_in[3];
    const float* w4 = (const float*)d_in[4];

    k_dwt  <<<dim3(32, 64), 1024>>>(x);
    k_wprep<<<dim3(64, 4), 256>>>(w1, w2, w3, w4);
    k_gemm <<<dim3(17, 17, 4), 256>>>();
    k_idwt <<<dim3(32, 16, 2), 512>>>((float*)d_out);
}